// round 1
// baseline (speedup 1.0000x reference)
#include <cuda_runtime.h>
#include <cmath>

// ---------------- problem constants ----------------
#define B_      2
#define N_      2048
#define CACHE_  512
#define KV_     2560            // CACHE_ + N_
#define DM_     768
#define NH_     12
#define HD_     64
#define FF_     3072
#define KSZ_    31
#define ROWS_   4096            // B_*N_
#define EPSF    1e-5f

// ---------------- scratch (__device__ globals; no cudaMalloc allowed) ----------------
__device__ float g_S0[(size_t)ROWS_ * DM_];    // running residual x
__device__ float g_S1[(size_t)ROWS_ * DM_];    // rmsnorm output
__device__ float g_S2[(size_t)ROWS_ * FF_];    // wide buffer (FF hidden / qkv / pw1)
__device__ float g_qrot[(size_t)ROWS_ * DM_];  // (B,N,H,D) roped queries
__device__ float g_krot[(size_t)B_ * KV_ * DM_]; // (B,KV,H,D) roped keys
__device__ float g_attn[(size_t)ROWS_ * DM_];  // attention output
__device__ float g_C1[(size_t)ROWS_ * DM_];    // conv buffers
__device__ float g_C2[(size_t)ROWS_ * DM_];
__device__ float g_bn[2 * DM_];                // [mean | invstd]

// ---------------- helpers ----------------
__device__ __forceinline__ float gelu_tanh(float x) {
    float x3 = x * x * x;
    float t  = tanhf(0.7978845608028654f * (x + 0.044715f * x3));
    return 0.5f * x * (1.0f + t);
}
__device__ __forceinline__ float sigmoidf_(float x) {
    return 1.0f / (1.0f + __expf(-x));
}

// ---------------- RMSNorm over DM_=768 ----------------
__global__ __launch_bounds__(256) void rmsnorm_k(const float* __restrict__ in,
                                                 const float* __restrict__ w,
                                                 float* __restrict__ out) {
    int row = blockIdx.x;
    const float* p = in + (size_t)row * DM_;
    float ss = 0.f;
    for (int i = threadIdx.x; i < DM_; i += 256) { float v = p[i]; ss = fmaf(v, v, ss); }
    for (int o = 16; o; o >>= 1) ss += __shfl_xor_sync(0xffffffffu, ss, o);
    __shared__ float red[8];
    if ((threadIdx.x & 31) == 0) red[threadIdx.x >> 5] = ss;
    __syncthreads();
    __shared__ float tots;
    if (threadIdx.x == 0) {
        float t = 0.f;
        #pragma unroll
        for (int i = 0; i < 8; i++) t += red[i];
        tots = t;
    }
    __syncthreads();
    float r = rsqrtf(tots / (float)DM_ + EPSF);
    float* q = out + (size_t)row * DM_;
    for (int i = threadIdx.x; i < DM_; i += 256) q[i] = p[i] * r * w[i];
}

// ---------------- SGEMM 128x128x16, 256 threads, 8x8/thread ----------------
// EPI: 0 = store, 1 = bias+gelu, 2 = 0.5*(x+bias)+R, 3 = +R, 4 = +bias
template <int EPI>
__global__ __launch_bounds__(256) void sgemm(const float* __restrict__ A,
                                             const float* __restrict__ Bm,
                                             const float* __restrict__ bias,
                                             const float* __restrict__ R,
                                             float* __restrict__ C,
                                             int M, int N, int K) {
    __shared__ float As[16][129];   // transposed, padded
    __shared__ float Bs[16][128];
    int tid = threadIdx.x;
    int tr = tid >> 4, tc = tid & 15;
    int aRow = tid >> 2;            // 0..63
    int aCol = (tid & 3) << 2;      // 0,4,8,12
    int bRow = tid >> 5;            // 0..7
    int bCol = (tid & 31) << 2;     // 0..124

    const float* Ab = A + (size_t)blockIdx.y * 128 * K;
    const float* Bb = Bm + (size_t)blockIdx.x * 128;

    float acc[8][8];
    #pragma unroll
    for (int i = 0; i < 8; i++)
        #pragma unroll
        for (int j = 0; j < 8; j++) acc[i][j] = 0.f;

    for (int kt = 0; kt < K; kt += 16) {
        #pragma unroll
        for (int p = 0; p < 2; p++) {
            float4 va = *(const float4*)(Ab + (size_t)(aRow + 64 * p) * K + kt + aCol);
            As[aCol + 0][aRow + 64 * p] = va.x;
            As[aCol + 1][aRow + 64 * p] = va.y;
            As[aCol + 2][aRow + 64 * p] = va.z;
            As[aCol + 3][aRow + 64 * p] = va.w;
        }
        #pragma unroll
        for (int p = 0; p < 2; p++) {
            float4 vb = *(const float4*)(Bb + (size_t)(kt + bRow + 8 * p) * N + bCol);
            *(float4*)&Bs[bRow + 8 * p][bCol] = vb;
        }
        __syncthreads();
        #pragma unroll
        for (int kk = 0; kk < 16; kk++) {
            float rm[8], rn[8];
            #pragma unroll
            for (int i = 0; i < 8; i++) rm[i] = As[kk][tr * 8 + i];
            #pragma unroll
            for (int j = 0; j < 8; j++) rn[j] = Bs[kk][tc * 8 + j];
            #pragma unroll
            for (int i = 0; i < 8; i++)
                #pragma unroll
                for (int j = 0; j < 8; j++) acc[i][j] = fmaf(rm[i], rn[j], acc[i][j]);
        }
        __syncthreads();
    }

    #pragma unroll
    for (int i = 0; i < 8; i++) {
        size_t row = (size_t)blockIdx.y * 128 + tr * 8 + i;
        #pragma unroll
        for (int j = 0; j < 8; j++) {
            size_t col = (size_t)blockIdx.x * 128 + tc * 8 + j;
            float v = acc[i][j];
            if (EPI == 1 || EPI == 2 || EPI == 4) v += bias[col];
            if (EPI == 1) v = gelu_tanh(v);
            if (EPI == 2) v = 0.5f * v + R[row * N + col];
            if (EPI == 3) v += R[row * N + col];
            C[row * N + col] = v;
        }
    }
}

// ---------------- post-QKV: per-head rmsnorm, RoPE, cache write ----------------
__global__ __launch_bounds__(64) void qkv_post_k(const float* __restrict__ qkv,
                                                 const float* __restrict__ qw,
                                                 const float* __restrict__ kw,
                                                 float* __restrict__ qrot,
                                                 float* __restrict__ krot,
                                                 float* __restrict__ outkv) {
    int row = blockIdx.x;        // b*N + n
    int h = blockIdx.y;
    int d = threadIdx.x;         // 0..63
    int b = row / N_, n = row % N_;
    const float* base = qkv + (size_t)row * (3 * DM_) + h * (HD_ * 3);
    float q = base[d * 3 + 0], k = base[d * 3 + 1], v = base[d * 3 + 2];
    float q2 = q * q, k2 = k * k;
    for (int o = 16; o; o >>= 1) {
        q2 += __shfl_xor_sync(0xffffffffu, q2, o);
        k2 += __shfl_xor_sync(0xffffffffu, k2, o);
    }
    __shared__ float red[4];
    if ((d & 31) == 0) { red[d >> 5] = q2; red[2 + (d >> 5)] = k2; }
    __syncthreads();
    float qn = q * rsqrtf((red[0] + red[1]) / (float)HD_ + EPSF) * qw[d];
    float kn = k * rsqrtf((red[2] + red[3]) / (float)HD_ + EPSF) * kw[d];
    __shared__ float sq[64], sk[64];
    sq[d] = qn; sk[d] = kn;
    __syncthreads();
    int pos = CACHE_ + n;
    int i = d & 31;
    float inv = __expf(-(float)i * 0.28782313662425572f);  // ln(10000)/32
    float ang = (float)pos * inv;
    float c = cosf(ang), s = sinf(ang);
    float qr, kr;
    if (d < 32) { qr = qn * c - sq[d + 32] * s; kr = kn * c - sk[d + 32] * s; }
    else        { qr = qn * c + sq[d - 32] * s; kr = kn * c + sk[d - 32] * s; }
    qrot[(((size_t)b * N_ + n) * NH_ + h) * HD_ + d] = qr;
    krot[(((size_t)b * KV_ + pos) * NH_ + h) * HD_ + d] = kr;
    size_t cb = (((size_t)b * KV_ + pos) * 2) * DM_ + h * HD_ + d;
    outkv[cb] = kn;          // k slot (normed, un-roped, as cached)
    outkv[cb + DM_] = v;     // v slot
}

// ---------------- cached KV: copy to output + rope K ----------------
__global__ __launch_bounds__(64) void cache_k(const float* __restrict__ cached,
                                              float* __restrict__ krot,
                                              float* __restrict__ outkv) {
    int row = blockIdx.x;        // b*CACHE + p
    int h = blockIdx.y;
    int d = threadIdx.x;
    int b = row / CACHE_, p = row % CACHE_;
    size_t src = (((size_t)b * CACHE_ + p) * 2) * DM_ + h * HD_ + d;
    float k = cached[src], v = cached[src + DM_];
    size_t dst = (((size_t)b * KV_ + p) * 2) * DM_ + h * HD_ + d;
    outkv[dst] = k;
    outkv[dst + DM_] = v;
    __shared__ float sk[64];
    sk[d] = k;
    __syncthreads();
    int i = d & 31;
    float inv = __expf(-(float)i * 0.28782313662425572f);
    float ang = (float)p * inv;
    float c = cosf(ang), s = sinf(ang);
    float kr = (d < 32) ? (k * c - sk[d + 32] * s) : (k * c + sk[d - 32] * s);
    krot[(((size_t)b * KV_ + p) * NH_ + h) * HD_ + d] = kr;
}

// ---------------- flash attention: 64 q-rows x full 2560 KV, d=64 ----------------
#define FLASH_SMEM ((64*64 + 64*68 + 64*64 + 64*64) * 4)
__global__ __launch_bounds__(256) void flash_attn(const float* __restrict__ Q,
                                                  const float* __restrict__ Kr,
                                                  const float* __restrict__ OUTKV,
                                                  float* __restrict__ O) {
    extern __shared__ float sm[];
    float* Qs = sm;              // [64][64]
    float* Ks = Qs + 64 * 64;    // [64][68]  (d-major)
    float* Vs = Ks + 64 * 68;    // [64][64]  (kv-major)
    float* Ps = Vs + 64 * 64;    // [64][64]
    int q0 = blockIdx.x * 64;
    int h = blockIdx.y;
    int b = blockIdx.z;
    int tid = threadIdx.x;
    int tr = tid >> 4, tc = tid & 15;

    for (int e = tid; e < 64 * 64; e += 256) {
        int r = e >> 6, d = e & 63;
        Qs[e] = Q[(((size_t)b * N_ + q0 + r) * NH_ + h) * HD_ + d];
    }
    float m[4], l[4], o[4][4];
    #pragma unroll
    for (int i = 0; i < 4; i++) {
        m[i] = -1e30f; l[i] = 0.f;
        #pragma unroll
        for (int j = 0; j < 4; j++) o[i][j] = 0.f;
    }

    for (int t = 0; t < KV_; t += 64) {
        __syncthreads();   // protect prev-iter Ps/Vs readers & first-iter Q
        for (int e = tid; e < 64 * 64; e += 256) {
            int n = e >> 6, d = e & 63;
            Ks[d * 68 + n] = Kr[(((size_t)b * KV_ + t + n) * NH_ + h) * HD_ + d];
            Vs[n * 64 + d] = OUTKV[(((size_t)b * KV_ + t + n) * 2 + 1) * DM_ + h * HD_ + d];
        }
        __syncthreads();

        float s[4][4];
        #pragma unroll
        for (int i = 0; i < 4; i++)
            #pragma unroll
            for (int j = 0; j < 4; j++) s[i][j] = 0.f;
        for (int kk = 0; kk < 64; kk++) {
            float rq[4];
            #pragma unroll
            for (int i = 0; i < 4; i++) rq[i] = Qs[(tr * 4 + i) * 64 + kk];
            float4 k4 = *(const float4*)&Ks[kk * 68 + tc * 4];
            float rk[4] = {k4.x, k4.y, k4.z, k4.w};
            #pragma unroll
            for (int i = 0; i < 4; i++)
                #pragma unroll
                for (int j = 0; j < 4; j++) s[i][j] = fmaf(rq[i], rk[j], s[i][j]);
        }
        #pragma unroll
        for (int i = 0; i < 4; i++) {
            #pragma unroll
            for (int j = 0; j < 4; j++) s[i][j] *= 0.125f;  // 1/sqrt(64)
            float mx = fmaxf(fmaxf(s[i][0], s[i][1]), fmaxf(s[i][2], s[i][3]));
            for (int off = 1; off < 16; off <<= 1)
                mx = fmaxf(mx, __shfl_xor_sync(0xffffffffu, mx, off));
            float mn = fmaxf(m[i], mx);
            float alpha = __expf(m[i] - mn);
            m[i] = mn;
            float ls = 0.f;
            #pragma unroll
            for (int j = 0; j < 4; j++) { float p = __expf(s[i][j] - mn); s[i][j] = p; ls += p; }
            for (int off = 1; off < 16; off <<= 1)
                ls += __shfl_xor_sync(0xffffffffu, ls, off);
            l[i] = l[i] * alpha + ls;
            #pragma unroll
            for (int j = 0; j < 4; j++) o[i][j] *= alpha;
            float4 pw = make_float4(s[i][0], s[i][1], s[i][2], s[i][3]);
            *(float4*)&Ps[(tr * 4 + i) * 64 + tc * 4] = pw;
        }
        __syncthreads();
        for (int kk = 0; kk < 64; kk++) {
            float pv[4];
            #pragma unroll
            for (int i = 0; i < 4; i++) pv[i] = Ps[(tr * 4 + i) * 64 + kk];
            float4 v4 = *(const float4*)&Vs[kk * 64 + tc * 4];
            float rv[4] = {v4.x, v4.y, v4.z, v4.w};
            #pragma unroll
            for (int i = 0; i < 4; i++)
                #pragma unroll
                for (int j = 0; j < 4; j++) o[i][j] = fmaf(pv[i], rv[j], o[i][j]);
        }
    }
    #pragma unroll
    for (int i = 0; i < 4; i++) {
        float inv_l = 1.f / l[i];
        int r = q0 + tr * 4 + i;
        #pragma unroll
        for (int j = 0; j < 4; j++)
            O[((size_t)b * N_ + r) * DM_ + h * HD_ + tc * 4 + j] = o[i][j] * inv_l;
    }
}

// ---------------- GLU: a * sigmoid(b) ----------------
__global__ void glu_k(const float* __restrict__ in, float* __restrict__ out) {
    size_t idx = (size_t)blockIdx.x * blockDim.x + threadIdx.x;
    if (idx >= (size_t)ROWS_ * DM_) return;
    size_t r = idx / DM_, c = idx % DM_;
    float a = in[r * (2 * DM_) + c];
    float b = in[r * (2 * DM_) + DM_ + c];
    out[idx] = a * sigmoidf_(b);
}

// ---------------- depthwise conv1d (KSZ=31, pad 15, per batch) ----------------
__global__ __launch_bounds__(256) void dwconv_k(const float* __restrict__ in,
                                                const float* __restrict__ wt,
                                                const float* __restrict__ bias,
                                                float* __restrict__ out) {
    int row = blockIdx.x;            // b*N + t
    int b = row / N_, t = row % N_;
    for (int c = threadIdx.x; c < DM_; c += 256) {
        float acc = bias[c];
        #pragma unroll
        for (int k = 0; k < KSZ_; k++) {
            int t2 = t + k - (KSZ_ / 2);
            if (t2 >= 0 && t2 < N_)
                acc = fmaf(in[((size_t)b * N_ + t2) * DM_ + c], wt[c * KSZ_ + k], acc);
        }
        out[(size_t)row * DM_ + c] = acc;
    }
}

// ---------------- batchnorm stats (mean/var over B*N per channel) ----------------
__global__ __launch_bounds__(256) void bnstats_k(const float* __restrict__ in,
                                                 float* __restrict__ stats) {
    int c = blockIdx.x;
    double s = 0.0, ss = 0.0;
    for (int r = threadIdx.x; r < ROWS_; r += 256) {
        float v = in[(size_t)r * DM_ + c];
        s += v; ss += (double)v * v;
    }
    for (int o = 16; o; o >>= 1) {
        s += __shfl_xor_sync(0xffffffffu, s, o);
        ss += __shfl_xor_sync(0xffffffffu, ss, o);
    }
    __shared__ double rs[8], rss[8];
    if ((threadIdx.x & 31) == 0) { rs[threadIdx.x >> 5] = s; rss[threadIdx.x >> 5] = ss; }
    __syncthreads();
    if (threadIdx.x == 0) {
        double S = 0.0, SS = 0.0;
        #pragma unroll
        for (int i = 0; i < 8; i++) { S += rs[i]; SS += rss[i]; }
        double mean = S / (double)ROWS_;
        double var = SS / (double)ROWS_ - mean * mean;
        stats[c] = (float)mean;
        stats[DM_ + c] = rsqrtf((float)var + EPSF);
    }
}

// ---------------- batchnorm apply + swish ----------------
__global__ void bnapply_k(const float* __restrict__ in, const float* __restrict__ stats,
                          const float* __restrict__ g, const float* __restrict__ bb,
                          float* __restrict__ out) {
    size_t idx = (size_t)blockIdx.x * blockDim.x + threadIdx.x;
    if (idx >= (size_t)ROWS_ * DM_) return;
    int c = (int)(idx % DM_);
    float y = (in[idx] - stats[c]) * stats[DM_ + c] * g[c] + bb[c];
    out[idx] = y * sigmoidf_(y);
}

// ---------------- host launcher ----------------
extern "C" void kernel_launch(void* const* d_in, const int* in_sizes, int n_in,
                              void* d_out, int out_size) {
    (void)out_size;
    const float* x = (const float*)d_in[0];
    // locate cached_kv by size signature (robust to mask/length presence)
    int ikv = 4;
    for (int i = 1; i < n_in; i++)
        if (in_sizes[i] == 786432) { ikv = i; break; }
    const float* cached_kv = (const float*)d_in[ikv];
    int w = ikv + 1;
    const float* ff1_norm_w = (const float*)d_in[w + 0];
    const float* ff1_w1     = (const float*)d_in[w + 1];
    const float* ff1_b1     = (const float*)d_in[w + 2];
    const float* ff1_w2     = (const float*)d_in[w + 3];
    const float* ff1_b2     = (const float*)d_in[w + 4];
    const float* attn_norm_w= (const float*)d_in[w + 5];
    const float* qkv_w      = (const float*)d_in[w + 6];
    const float* out_w      = (const float*)d_in[w + 7];
    const float* q_norm_w   = (const float*)d_in[w + 8];
    const float* k_norm_w   = (const float*)d_in[w + 9];
    const float* conv_norm_w= (const float*)d_in[w + 10];
    const float* pw1_w      = (const float*)d_in[w + 11];
    const float* pw1_b      = (const float*)d_in[w + 12];
    const float* dw_w       = (const float*)d_in[w + 13];
    const float* dw_b       = (const float*)d_in[w + 14];
    const float* bn_g       = (const float*)d_in[w + 15];
    const float* bn_b       = (const float*)d_in[w + 16];
    const float* pw2_w      = (const float*)d_in[w + 17];
    const float* pw2_b      = (const float*)d_in[w + 18];
    const float* ff2_norm_w = (const float*)d_in[w + 19];
    const float* ff2_w1     = (const float*)d_in[w + 20];
    const float* ff2_b1     = (const float*)d_in[w + 21];
    const float* ff2_w2     = (const float*)d_in[w + 22];
    const float* ff2_b2     = (const float*)d_in[w + 23];
    const float* out_norm_w = (const float*)d_in[w + 24];

    float* out_x  = (float*)d_out;
    float* out_kv = out_x + (size_t)B_ * N_ * DM_;

    float *S0, *S1, *S2, *QR, *KR, *AT, *C1, *C2, *BN;
    cudaGetSymbolAddress((void**)&S0, g_S0);
    cudaGetSymbolAddress((void**)&S1, g_S1);
    cudaGetSymbolAddress((void**)&S2, g_S2);
    cudaGetSymbolAddress((void**)&QR, g_qrot);
    cudaGetSymbolAddress((void**)&KR, g_krot);
    cudaGetSymbolAddress((void**)&AT, g_attn);
    cudaGetSymbolAddress((void**)&C1, g_C1);
    cudaGetSymbolAddress((void**)&C2, g_C2);
    cudaGetSymbolAddress((void**)&BN, g_bn);

    cudaFuncSetAttribute(flash_attn, cudaFuncAttributeMaxDynamicSharedMemorySize, FLASH_SMEM);

    const int EW_GRID = (int)(((size_t)ROWS_ * DM_ + 255) / 256);

    // ---- FF1 ----
    rmsnorm_k<<<ROWS_, 256>>>(x, ff1_norm_w, S1);
    sgemm<1><<<dim3(FF_ / 128, ROWS_ / 128), 256>>>(S1, ff1_w1, ff1_b1, nullptr, S2, ROWS_, FF_, DM_);
    sgemm<2><<<dim3(DM_ / 128, ROWS_ / 128), 256>>>(S2, ff1_w2, ff1_b2, x, S0, ROWS_, DM_, FF_);

    // ---- attention ----
    rmsnorm_k<<<ROWS_, 256>>>(S0, attn_norm_w, S1);
    sgemm<0><<<dim3((3 * DM_) / 128, ROWS_ / 128), 256>>>(S1, qkv_w, nullptr, nullptr, S2, ROWS_, 3 * DM_, DM_);
    qkv_post_k<<<dim3(ROWS_, NH_), 64>>>(S2, q_norm_w, k_norm_w, QR, KR, out_kv);
    cache_k<<<dim3(B_ * CACHE_, NH_), 64>>>(cached_kv, KR, out_kv);
    flash_attn<<<dim3(N_ / 64, NH_, B_), 256, FLASH_SMEM>>>(QR, KR, out_kv, AT);
    sgemm<3><<<dim3(DM_ / 128, ROWS_ / 128), 256>>>(AT, out_w, nullptr, S0, S0, ROWS_, DM_, DM_);

    // ---- conv module ----
    rmsnorm_k<<<ROWS_, 256>>>(S0, conv_norm_w, S1);
    sgemm<4><<<dim3((2 * DM_) / 128, ROWS_ / 128), 256>>>(S1, pw1_w, pw1_b, nullptr, S2, ROWS_, 2 * DM_, DM_);
    glu_k<<<EW_GRID, 256>>>(S2, C1);
    dwconv_k<<<ROWS_, 256>>>(C1, dw_w, dw_b, C2);
    bnstats_k<<<DM_, 256>>>(C2, BN);
    bnapply_k<<<EW_GRID, 256>>>(C2, BN, bn_g, bn_b, C1);
    sgemm<4><<<dim3(DM_ / 128, ROWS_ / 128), 256>>>(C1, pw2_w, pw2_b, nullptr, S0, ROWS_, DM_, DM_);

    // ---- FF2 ----
    rmsnorm_k<<<ROWS_, 256>>>(S0, ff2_norm_w, S1);
    sgemm<1><<<dim3(FF_ / 128, ROWS_ / 128), 256>>>(S1, ff2_w1, ff2_b1, nullptr, S2, ROWS_, FF_, DM_);
    sgemm<2><<<dim3(DM_ / 128, ROWS_ / 128), 256>>>(S2, ff2_w2, ff2_b2, S0, S0, ROWS_, DM_, FF_);

    // ---- final norm ----
    rmsnorm_k<<<ROWS_, 256>>>(S0, out_norm_w, out_x);
}

// round 2
// speedup vs baseline: 1.9385x; 1.9385x over previous
#include <cuda_runtime.h>
#include <cstdint>
#include <cmath>

// ---------------- problem constants ----------------
#define B_      2
#define N_      2048
#define CACHE_  512
#define KV_     2560            // CACHE_ + N_
#define DM_     768
#define NH_     12
#define HD_     64
#define FF_     3072
#define KSZ_    31
#define ROWS_   4096            // B_*N_
#define EPSF    1e-5f

// ---------------- scratch (__device__ globals; no cudaMalloc allowed) ----------------
__device__ float g_S0[(size_t)ROWS_ * DM_];    // running residual x
__device__ float g_S1[(size_t)ROWS_ * DM_];    // rmsnorm output
__device__ float g_S2[(size_t)ROWS_ * FF_];    // wide buffer (FF hidden / qkv / pw1)
__device__ float g_qrot[(size_t)ROWS_ * DM_];  // (B,N,H,D) roped queries
__device__ float g_krot[(size_t)B_ * KV_ * DM_]; // (B,KV,H,D) roped keys
__device__ float g_attn[(size_t)ROWS_ * DM_];  // attention output
__device__ float g_C1[(size_t)ROWS_ * DM_];    // conv buffers
__device__ float g_C2[(size_t)ROWS_ * DM_];
__device__ float g_bn[2 * DM_];                // [mean | invstd]

// ---------------- helpers ----------------
__device__ __forceinline__ float gelu_tanh(float x) {
    float x3 = x * x * x;
    float t  = tanhf(0.7978845608028654f * (x + 0.044715f * x3));
    return 0.5f * x * (1.0f + t);
}
__device__ __forceinline__ float sigmoidf_(float x) {
    return 1.0f / (1.0f + __expf(-x));
}
__device__ __forceinline__ uint32_t f2tf32(float x) {
    uint32_t u;
    asm("cvt.rna.tf32.f32 %0, %1;" : "=r"(u) : "f"(x));
    return u;
}
__device__ __forceinline__ void split_tf32(float x, uint32_t& hi, uint32_t& lo) {
    hi = f2tf32(x);
    float rem = x - __uint_as_float(hi);
    lo = f2tf32(rem);
}
__device__ __forceinline__ void mma_tf32(float (&c)[4], const uint32_t (&a)[4], const uint32_t (&b)[2]) {
    asm volatile(
        "mma.sync.aligned.m16n8k8.row.col.f32.tf32.tf32.f32 "
        "{%0,%1,%2,%3}, {%4,%5,%6,%7}, {%8,%9}, {%0,%1,%2,%3};\n"
        : "+f"(c[0]), "+f"(c[1]), "+f"(c[2]), "+f"(c[3])
        : "r"(a[0]), "r"(a[1]), "r"(a[2]), "r"(a[3]), "r"(b[0]), "r"(b[1]));
}

// ---------------- RMSNorm over DM_=768 ----------------
__global__ __launch_bounds__(256) void rmsnorm_k(const float* __restrict__ in,
                                                 const float* __restrict__ w,
                                                 float* __restrict__ out) {
    int row = blockIdx.x;
    const float* p = in + (size_t)row * DM_;
    float ss = 0.f;
    for (int i = threadIdx.x; i < DM_; i += 256) { float v = p[i]; ss = fmaf(v, v, ss); }
    for (int o = 16; o; o >>= 1) ss += __shfl_xor_sync(0xffffffffu, ss, o);
    __shared__ float red[8];
    if ((threadIdx.x & 31) == 0) red[threadIdx.x >> 5] = ss;
    __syncthreads();
    __shared__ float tots;
    if (threadIdx.x == 0) {
        float t = 0.f;
        #pragma unroll
        for (int i = 0; i < 8; i++) t += red[i];
        tots = t;
    }
    __syncthreads();
    float r = rsqrtf(tots / (float)DM_ + EPSF);
    float* q = out + (size_t)row * DM_;
    for (int i = threadIdx.x; i < DM_; i += 256) q[i] = p[i] * r * w[i];
}

// ---------------- tensor-core GEMM 128x128x16, 3xTF32 split ----------------
// 8 warps, each computes a 64x32 tile via 4x4 grid of m16n8k8 mma.
// EPI: 0 = store, 1 = bias+gelu, 2 = 0.5*(x+bias)+R, 3 = +R, 4 = +bias
template <int EPI>
__global__ __launch_bounds__(256) void gemm_tc(const float* __restrict__ A,
                                               const float* __restrict__ Bm,
                                               const float* __restrict__ bias,
                                               const float* __restrict__ R,
                                               float* __restrict__ C,
                                               int M, int N, int K) {
    __shared__ float As[16][136];   // [k][m], stride 136 -> conflict-free frag reads
    __shared__ float Bs[16][136];   // [k][n]
    int tid = threadIdx.x;
    int warp = tid >> 5, lane = tid & 31;
    int wm = warp >> 2;             // 0..1 (64-row halves)
    int wn = warp & 3;              // 0..3 (32-col quarters)
    int g = lane >> 2, tg = lane & 3;

    const float* Ab = A + (size_t)blockIdx.y * 128 * K;
    const float* Bb = Bm + (size_t)blockIdx.x * 128;

    float acc[4][4][4];
    #pragma unroll
    for (int i = 0; i < 4; i++)
        #pragma unroll
        for (int j = 0; j < 4; j++)
            #pragma unroll
            for (int r = 0; r < 4; r++) acc[i][j][r] = 0.f;

    for (int kt = 0; kt < K; kt += 16) {
        #pragma unroll
        for (int p = 0; p < 2; p++) {
            int linear = tid + p * 256;
            int row = linear >> 2;            // 0..127
            int c4 = (linear & 3) << 2;       // 0,4,8,12
            float4 v = *(const float4*)(Ab + (size_t)row * K + kt + c4);
            As[c4 + 0][row] = v.x;
            As[c4 + 1][row] = v.y;
            As[c4 + 2][row] = v.z;
            As[c4 + 3][row] = v.w;
        }
        #pragma unroll
        for (int p = 0; p < 2; p++) {
            int linear = tid + p * 256;
            int br = linear >> 5;             // 0..15
            int bc = (linear & 31) << 2;      // 0..124
            float4 v = *(const float4*)(Bb + (size_t)(kt + br) * N + bc);
            *(float4*)&Bs[br][bc] = v;
        }
        __syncthreads();

        #pragma unroll
        for (int ks = 0; ks < 2; ks++) {
            int k0 = ks * 8;
            // B fragments (hi/lo)
            uint32_t bh[4][2], bl[4][2];
            #pragma unroll
            for (int j = 0; j < 4; j++) {
                int col = wn * 32 + j * 8 + g;
                float b0 = Bs[k0 + tg][col];
                float b1 = Bs[k0 + tg + 4][col];
                split_tf32(b0, bh[j][0], bl[j][0]);
                split_tf32(b1, bh[j][1], bl[j][1]);
            }
            #pragma unroll
            for (int i = 0; i < 4; i++) {
                int r0 = wm * 64 + i * 16 + g;
                float a0 = As[k0 + tg][r0];
                float a1 = As[k0 + tg][r0 + 8];
                float a2 = As[k0 + tg + 4][r0];
                float a3 = As[k0 + tg + 4][r0 + 8];
                uint32_t ah[4], al[4];
                split_tf32(a0, ah[0], al[0]);
                split_tf32(a1, ah[1], al[1]);
                split_tf32(a2, ah[2], al[2]);
                split_tf32(a3, ah[3], al[3]);
                #pragma unroll
                for (int j = 0; j < 4; j++) {
                    mma_tf32(acc[i][j], ah, bl[j]);   // hi*lo
                    mma_tf32(acc[i][j], al, bh[j]);   // lo*hi
                    mma_tf32(acc[i][j], ah, bh[j]);   // hi*hi
                }
            }
        }
        __syncthreads();
    }

    // epilogue
    #pragma unroll
    for (int i = 0; i < 4; i++) {
        #pragma unroll
        for (int j = 0; j < 4; j++) {
            size_t row0 = (size_t)blockIdx.y * 128 + wm * 64 + i * 16 + g;
            size_t col0 = (size_t)blockIdx.x * 128 + wn * 32 + j * 8 + 2 * tg;
            #pragma unroll
            for (int h = 0; h < 2; h++) {           // h=0: rows g, h=1: rows g+8
                size_t row = row0 + h * 8;
                float v0 = acc[i][j][h * 2 + 0];
                float v1 = acc[i][j][h * 2 + 1];
                if (EPI == 1 || EPI == 2 || EPI == 4) { v0 += bias[col0]; v1 += bias[col0 + 1]; }
                if (EPI == 1) { v0 = gelu_tanh(v0); v1 = gelu_tanh(v1); }
                if (EPI == 2) {
                    v0 = 0.5f * v0 + R[row * N + col0];
                    v1 = 0.5f * v1 + R[row * N + col0 + 1];
                }
                if (EPI == 3) {
                    v0 += R[row * N + col0];
                    v1 += R[row * N + col0 + 1];
                }
                *(float2*)&C[row * N + col0] = make_float2(v0, v1);
            }
        }
    }
}

// ---------------- post-QKV: per-head rmsnorm, RoPE, cache write ----------------
__global__ __launch_bounds__(64) void qkv_post_k(const float* __restrict__ qkv,
                                                 const float* __restrict__ qw,
                                                 const float* __restrict__ kw,
                                                 float* __restrict__ qrot,
                                                 float* __restrict__ krot,
                                                 float* __restrict__ outkv) {
    int row = blockIdx.x;        // b*N + n
    int h = blockIdx.y;
    int d = threadIdx.x;         // 0..63
    int b = row / N_, n = row % N_;
    const float* base = qkv + (size_t)row * (3 * DM_) + h * (HD_ * 3);
    float q = base[d * 3 + 0], k = base[d * 3 + 1], v = base[d * 3 + 2];
    float q2 = q * q, k2 = k * k;
    for (int o = 16; o; o >>= 1) {
        q2 += __shfl_xor_sync(0xffffffffu, q2, o);
        k2 += __shfl_xor_sync(0xffffffffu, k2, o);
    }
    __shared__ float red[4];
    if ((d & 31) == 0) { red[d >> 5] = q2; red[2 + (d >> 5)] = k2; }
    __syncthreads();
    float qn = q * rsqrtf((red[0] + red[1]) / (float)HD_ + EPSF) * qw[d];
    float kn = k * rsqrtf((red[2] + red[3]) / (float)HD_ + EPSF) * kw[d];
    __shared__ float sq[64], sk[64];
    sq[d] = qn; sk[d] = kn;
    __syncthreads();
    int pos = CACHE_ + n;
    int i = d & 31;
    float inv = __expf(-(float)i * 0.28782313662425572f);  // ln(10000)/32
    float ang = (float)pos * inv;
    float c = cosf(ang), s = sinf(ang);
    float qr, kr;
    if (d < 32) { qr = qn * c - sq[d + 32] * s; kr = kn * c - sk[d + 32] * s; }
    else        { qr = qn * c + sq[d - 32] * s; kr = kn * c + sk[d - 32] * s; }
    qrot[(((size_t)b * N_ + n) * NH_ + h) * HD_ + d] = qr;
    krot[(((size_t)b * KV_ + pos) * NH_ + h) * HD_ + d] = kr;
    size_t cb = (((size_t)b * KV_ + pos) * 2) * DM_ + h * HD_ + d;
    outkv[cb] = kn;          // k slot (normed, un-roped, as cached)
    outkv[cb + DM_] = v;     // v slot
}

// ---------------- cached KV: copy to output + rope K ----------------
__global__ __launch_bounds__(64) void cache_k(const float* __restrict__ cached,
                                              float* __restrict__ krot,
                                              float* __restrict__ outkv) {
    int row = blockIdx.x;        // b*CACHE + p
    int h = blockIdx.y;
    int d = threadIdx.x;
    int b = row / CACHE_, p = row % CACHE_;
    size_t src = (((size_t)b * CACHE_ + p) * 2) * DM_ + h * HD_ + d;
    float k = cached[src], v = cached[src + DM_];
    size_t dst = (((size_t)b * KV_ + p) * 2) * DM_ + h * HD_ + d;
    outkv[dst] = k;
    outkv[dst + DM_] = v;
    __shared__ float sk[64];
    sk[d] = k;
    __syncthreads();
    int i = d & 31;
    float inv = __expf(-(float)i * 0.28782313662425572f);
    float ang = (float)p * inv;
    float c = cosf(ang), s = sinf(ang);
    float kr = (d < 32) ? (k * c - sk[d + 32] * s) : (k * c + sk[d - 32] * s);
    krot[(((size_t)b * KV_ + p) * NH_ + h) * HD_ + d] = kr;
}

// ---------------- flash attention: 64 q-rows x full 2560 KV, d=64 ----------------
#define FLASH_SMEM ((64*64 + 64*68 + 64*64 + 64*64) * 4)
__global__ __launch_bounds__(256) void flash_attn(const float* __restrict__ Q,
                                                  const float* __restrict__ Kr,
                                                  const float* __restrict__ OUTKV,
                                                  float* __restrict__ O) {
    extern __shared__ float sm[];
    float* Qs = sm;              // [64][64]
    float* Ks = Qs + 64 * 64;    // [64][68]  (d-major)
    float* Vs = Ks + 64 * 68;    // [64][64]  (kv-major)
    float* Ps = Vs + 64 * 64;    // [64][64]
    int q0 = blockIdx.x * 64;
    int h = blockIdx.y;
    int b = blockIdx.z;
    int tid = threadIdx.x;
    int tr = tid >> 4, tc = tid & 15;

    for (int e = tid; e < 64 * 64; e += 256) {
        int r = e >> 6, d = e & 63;
        Qs[e] = Q[(((size_t)b * N_ + q0 + r) * NH_ + h) * HD_ + d];
    }
    float m[4], l[4], o[4][4];
    #pragma unroll
    for (int i = 0; i < 4; i++) {
        m[i] = -1e30f; l[i] = 0.f;
        #pragma unroll
        for (int j = 0; j < 4; j++) o[i][j] = 0.f;
    }

    for (int t = 0; t < KV_; t += 64) {
        __syncthreads();   // protect prev-iter Ps/Vs readers & first-iter Q
        for (int e = tid; e < 64 * 64; e += 256) {
            int n = e >> 6, d = e & 63;
            Ks[d * 68 + n] = Kr[(((size_t)b * KV_ + t + n) * NH_ + h) * HD_ + d];
            Vs[n * 64 + d] = OUTKV[(((size_t)b * KV_ + t + n) * 2 + 1) * DM_ + h * HD_ + d];
        }
        __syncthreads();

        float s[4][4];
        #pragma unroll
        for (int i = 0; i < 4; i++)
            #pragma unroll
            for (int j = 0; j < 4; j++) s[i][j] = 0.f;
        for (int kk = 0; kk < 64; kk++) {
            float rq[4];
            #pragma unroll
            for (int i = 0; i < 4; i++) rq[i] = Qs[(tr * 4 + i) * 64 + kk];
            float4 k4 = *(const float4*)&Ks[kk * 68 + tc * 4];
            float rk[4] = {k4.x, k4.y, k4.z, k4.w};
            #pragma unroll
            for (int i = 0; i < 4; i++)
                #pragma unroll
                for (int j = 0; j < 4; j++) s[i][j] = fmaf(rq[i], rk[j], s[i][j]);
        }
        #pragma unroll
        for (int i = 0; i < 4; i++) {
            #pragma unroll
            for (int j = 0; j < 4; j++) s[i][j] *= 0.125f;  // 1/sqrt(64)
            float mx = fmaxf(fmaxf(s[i][0], s[i][1]), fmaxf(s[i][2], s[i][3]));
            for (int off = 1; off < 16; off <<= 1)
                mx = fmaxf(mx, __shfl_xor_sync(0xffffffffu, mx, off));
            float mn = fmaxf(m[i], mx);
            float alpha = __expf(m[i] - mn);
            m[i] = mn;
            float ls = 0.f;
            #pragma unroll
            for (int j = 0; j < 4; j++) { float p = __expf(s[i][j] - mn); s[i][j] = p; ls += p; }
            for (int off = 1; off < 16; off <<= 1)
                ls += __shfl_xor_sync(0xffffffffu, ls, off);
            l[i] = l[i] * alpha + ls;
            #pragma unroll
            for (int j = 0; j < 4; j++) o[i][j] *= alpha;
            float4 pw = make_float4(s[i][0], s[i][1], s[i][2], s[i][3]);
            *(float4*)&Ps[(tr * 4 + i) * 64 + tc * 4] = pw;
        }
        __syncthreads();
        for (int kk = 0; kk < 64; kk++) {
            float pv[4];
            #pragma unroll
            for (int i = 0; i < 4; i++) pv[i] = Ps[(tr * 4 + i) * 64 + kk];
            float4 v4 = *(const float4*)&Vs[kk * 64 + tc * 4];
            float rv[4] = {v4.x, v4.y, v4.z, v4.w};
            #pragma unroll
            for (int i = 0; i < 4; i++)
                #pragma unroll
                for (int j = 0; j < 4; j++) o[i][j] = fmaf(pv[i], rv[j], o[i][j]);
        }
    }
    #pragma unroll
    for (int i = 0; i < 4; i++) {
        float inv_l = 1.f / l[i];
        int r = q0 + tr * 4 + i;
        #pragma unroll
        for (int j = 0; j < 4; j++)
            O[((size_t)b * N_ + r) * DM_ + h * HD_ + tc * 4 + j] = o[i][j] * inv_l;
    }
}

// ---------------- GLU: a * sigmoid(b) ----------------
__global__ void glu_k(const float* __restrict__ in, float* __restrict__ out) {
    size_t idx = (size_t)blockIdx.x * blockDim.x + threadIdx.x;
    if (idx >= (size_t)ROWS_ * DM_) return;
    size_t r = idx / DM_, c = idx % DM_;
    float a = in[r * (2 * DM_) + c];
    float b = in[r * (2 * DM_) + DM_ + c];
    out[idx] = a * sigmoidf_(b);
}

// ---------------- depthwise conv1d (KSZ=31, pad 15, per batch) ----------------
__global__ __launch_bounds__(256) void dwconv_k(const float* __restrict__ in,
                                                const float* __restrict__ wt,
                                                const float* __restrict__ bias,
                                                float* __restrict__ out) {
    int row = blockIdx.x;            // b*N + t
    int b = row / N_, t = row % N_;
    for (int c = threadIdx.x; c < DM_; c += 256) {
        float acc = bias[c];
        #pragma unroll
        for (int k = 0; k < KSZ_; k++) {
            int t2 = t + k - (KSZ_ / 2);
            if (t2 >= 0 && t2 < N_)
                acc = fmaf(in[((size_t)b * N_ + t2) * DM_ + c], wt[c * KSZ_ + k], acc);
        }
        out[(size_t)row * DM_ + c] = acc;
    }
}

// ---------------- batchnorm stats (mean/var over B*N per channel) ----------------
__global__ __launch_bounds__(256) void bnstats_k(const float* __restrict__ in,
                                                 float* __restrict__ stats) {
    int c = blockIdx.x;
    double s = 0.0, ss = 0.0;
    for (int r = threadIdx.x; r < ROWS_; r += 256) {
        float v = in[(size_t)r * DM_ + c];
        s += v; ss += (double)v * v;
    }
    for (int o = 16; o; o >>= 1) {
        s += __shfl_xor_sync(0xffffffffu, s, o);
        ss += __shfl_xor_sync(0xffffffffu, ss, o);
    }
    __shared__ double rs[8], rss[8];
    if ((threadIdx.x & 31) == 0) { rs[threadIdx.x >> 5] = s; rss[threadIdx.x >> 5] = ss; }
    __syncthreads();
    if (threadIdx.x == 0) {
        double S = 0.0, SS = 0.0;
        #pragma unroll
        for (int i = 0; i < 8; i++) { S += rs[i]; SS += rss[i]; }
        double mean = S / (double)ROWS_;
        double var = SS / (double)ROWS_ - mean * mean;
        stats[c] = (float)mean;
        stats[DM_ + c] = rsqrtf((float)var + EPSF);
    }
}

// ---------------- batchnorm apply + swish ----------------
__global__ void bnapply_k(const float* __restrict__ in, const float* __restrict__ stats,
                          const float* __restrict__ g, const float* __restrict__ bb,
                          float* __restrict__ out) {
    size_t idx = (size_t)blockIdx.x * blockDim.x + threadIdx.x;
    if (idx >= (size_t)ROWS_ * DM_) return;
    int c = (int)(idx % DM_);
    float y = (in[idx] - stats[c]) * stats[DM_ + c] * g[c] + bb[c];
    out[idx] = y * sigmoidf_(y);
}

// ---------------- host launcher ----------------
extern "C" void kernel_launch(void* const* d_in, const int* in_sizes, int n_in,
                              void* d_out, int out_size) {
    (void)out_size;
    const float* x = (const float*)d_in[0];
    int ikv = 4;
    for (int i = 1; i < n_in; i++)
        if (in_sizes[i] == 786432) { ikv = i; break; }
    const float* cached_kv = (const float*)d_in[ikv];
    int w = ikv + 1;
    const float* ff1_norm_w = (const float*)d_in[w + 0];
    const float* ff1_w1     = (const float*)d_in[w + 1];
    const float* ff1_b1     = (const float*)d_in[w + 2];
    const float* ff1_w2     = (const float*)d_in[w + 3];
    const float* ff1_b2     = (const float*)d_in[w + 4];
    const float* attn_norm_w= (const float*)d_in[w + 5];
    const float* qkv_w      = (const float*)d_in[w + 6];
    const float* out_w      = (const float*)d_in[w + 7];
    const float* q_norm_w   = (const float*)d_in[w + 8];
    const float* k_norm_w   = (const float*)d_in[w + 9];
    const float* conv_norm_w= (const float*)d_in[w + 10];
    const float* pw1_w      = (const float*)d_in[w + 11];
    const float* pw1_b      = (const float*)d_in[w + 12];
    const float* dw_w       = (const float*)d_in[w + 13];
    const float* dw_b       = (const float*)d_in[w + 14];
    const float* bn_g       = (const float*)d_in[w + 15];
    const float* bn_b       = (const float*)d_in[w + 16];
    const float* pw2_w      = (const float*)d_in[w + 17];
    const float* pw2_b      = (const float*)d_in[w + 18];
    const float* ff2_norm_w = (const float*)d_in[w + 19];
    const float* ff2_w1     = (const float*)d_in[w + 20];
    const float* ff2_b1     = (const float*)d_in[w + 21];
    const float* ff2_w2     = (const float*)d_in[w + 22];
    const float* ff2_b2     = (const float*)d_in[w + 23];
    const float* out_norm_w = (const float*)d_in[w + 24];

    float* out_x  = (float*)d_out;
    float* out_kv = out_x + (size_t)B_ * N_ * DM_;

    float *S0, *S1, *S2, *QR, *KR, *AT, *C1, *C2, *BN;
    cudaGetSymbolAddress((void**)&S0, g_S0);
    cudaGetSymbolAddress((void**)&S1, g_S1);
    cudaGetSymbolAddress((void**)&S2, g_S2);
    cudaGetSymbolAddress((void**)&QR, g_qrot);
    cudaGetSymbolAddress((void**)&KR, g_krot);
    cudaGetSymbolAddress((void**)&AT, g_attn);
    cudaGetSymbolAddress((void**)&C1, g_C1);
    cudaGetSymbolAddress((void**)&C2, g_C2);
    cudaGetSymbolAddress((void**)&BN, g_bn);

    cudaFuncSetAttribute(flash_attn, cudaFuncAttributeMaxDynamicSharedMemorySize, FLASH_SMEM);

    const int EW_GRID = (int)(((size_t)ROWS_ * DM_ + 255) / 256);

    // ---- FF1 ----
    rmsnorm_k<<<ROWS_, 256>>>(x, ff1_norm_w, S1);
    gemm_tc<1><<<dim3(FF_ / 128, ROWS_ / 128), 256>>>(S1, ff1_w1, ff1_b1, nullptr, S2, ROWS_, FF_, DM_);
    gemm_tc<2><<<dim3(DM_ / 128, ROWS_ / 128), 256>>>(S2, ff1_w2, ff1_b2, x, S0, ROWS_, DM_, FF_);

    // ---- attention ----
    rmsnorm_k<<<ROWS_, 256>>>(S0, attn_norm_w, S1);
    gemm_tc<0><<<dim3((3 * DM_) / 128, ROWS_ / 128), 256>>>(S1, qkv_w, nullptr, nullptr, S2, ROWS_, 3 * DM_, DM_);
    qkv_post_k<<<dim3(ROWS_, NH_), 64>>>(S2, q_norm_w, k_norm_w, QR, KR, out_kv);
    cache_k<<<dim3(B_ * CACHE_, NH_), 64>>>(cached_kv, KR, out_kv);
    flash_attn<<<dim3(N_ / 64, NH_, B_), 256, FLASH_SMEM>>>(QR, KR, out_kv, AT);
    gemm_tc<3><<<dim3(DM_ / 128, ROWS_ / 128), 256>>>(AT, out_w, nullptr, S0, S0, ROWS_, DM_, DM_);

    // ---- conv module ----
    rmsnorm_k<<<ROWS_, 256>>>(S0, conv_norm_w, S1);
    gemm_tc<4><<<dim3((2 * DM_) / 128, ROWS_ / 128), 256>>>(S1, pw1_w, pw1_b, nullptr, S2, ROWS_, 2 * DM_, DM_);
    glu_k<<<EW_GRID, 256>>>(S2, C1);
    dwconv_k<<<ROWS_, 256>>>(C1, dw_w, dw_b, C2);
    bnstats_k<<<DM_, 256>>>(C2, BN);
    bnapply_k<<<EW_GRID, 256>>>(C2, BN, bn_g, bn_b, C1);
    gemm_tc<4><<<dim3(DM_ / 128, ROWS_ / 128), 256>>>(C1, pw2_w, pw2_b, nullptr, S0, ROWS_, DM_, DM_);

    // ---- FF2 ----
    rmsnorm_k<<<ROWS_, 256>>>(S0, ff2_norm_w, S1);
    gemm_tc<1><<<dim3(FF_ / 128, ROWS_ / 128), 256>>>(S1, ff2_w1, ff2_b1, nullptr, S2, ROWS_, FF_, DM_);
    gemm_tc<2><<<dim3(DM_ / 128, ROWS_ / 128), 256>>>(S2, ff2_w2, ff2_b2, S0, S0, ROWS_, DM_, FF_);

    // ---- final norm ----
    rmsnorm_k<<<ROWS_, 256>>>(S0, out_norm_w, out_x);
}

// round 3
// speedup vs baseline: 2.1114x; 1.0892x over previous
#include <cuda_runtime.h>
#include <cstdint>
#include <cmath>

// ---------------- problem constants ----------------
#define B_      2
#define N_      2048
#define CACHE_  512
#define KV_     2560            // CACHE_ + N_
#define DM_     768
#define NH_     12
#define HD_     64
#define FF_     3072
#define KSZ_    31
#define ROWS_   4096            // B_*N_
#define EPSF    1e-5f

// ---------------- scratch ----------------
__device__ float g_S0[(size_t)ROWS_ * DM_];
__device__ float g_S1[(size_t)ROWS_ * DM_];
__device__ float g_S2[(size_t)ROWS_ * FF_];
__device__ float g_qrot[(size_t)ROWS_ * DM_];
__device__ float g_krot[(size_t)B_ * KV_ * DM_];
__device__ float g_attn[(size_t)ROWS_ * DM_];
__device__ float g_C1[(size_t)ROWS_ * DM_];
__device__ float g_C2[(size_t)ROWS_ * DM_];
__device__ float g_bn[2 * DM_];

// ---------------- helpers ----------------
__device__ __forceinline__ float gelu_tanh(float x) {
    float x3 = x * x * x;
    float t  = tanhf(0.7978845608028654f * (x + 0.044715f * x3));
    return 0.5f * x * (1.0f + t);
}
__device__ __forceinline__ float sigmoidf_(float x) {
    return 1.0f / (1.0f + __expf(-x));
}
__device__ __forceinline__ float ex2f_(float x) {
    float y;
    asm("ex2.approx.f32 %0, %1;" : "=f"(y) : "f"(x));
    return y;
}
__device__ __forceinline__ uint32_t f2tf32(float x) {
    uint32_t u;
    asm("cvt.rna.tf32.f32 %0, %1;" : "=r"(u) : "f"(x));
    return u;
}
__device__ __forceinline__ void split_tf32(float x, uint32_t& hi, uint32_t& lo) {
    hi = f2tf32(x);
    float rem = x - __uint_as_float(hi);
    lo = f2tf32(rem);
}
__device__ __forceinline__ void mma_tf32(float (&c)[4], const uint32_t (&a)[4], const uint32_t (&b)[2]) {
    asm volatile(
        "mma.sync.aligned.m16n8k8.row.col.f32.tf32.tf32.f32 "
        "{%0,%1,%2,%3}, {%4,%5,%6,%7}, {%8,%9}, {%0,%1,%2,%3};\n"
        : "+f"(c[0]), "+f"(c[1]), "+f"(c[2]), "+f"(c[3])
        : "r"(a[0]), "r"(a[1]), "r"(a[2]), "r"(a[3]), "r"(b[0]), "r"(b[1]));
}

// ---------------- RMSNorm over DM_=768 (float4) ----------------
__global__ __launch_bounds__(192) void rmsnorm_k(const float* __restrict__ in,
                                                 const float* __restrict__ w,
                                                 float* __restrict__ out) {
    int row = blockIdx.x;
    const float4* p = (const float4*)(in + (size_t)row * DM_);
    float4 v = p[threadIdx.x];
    float ss = v.x * v.x + v.y * v.y + v.z * v.z + v.w * v.w;
    for (int o = 16; o; o >>= 1) ss += __shfl_xor_sync(0xffffffffu, ss, o);
    __shared__ float red[6];
    if ((threadIdx.x & 31) == 0) red[threadIdx.x >> 5] = ss;
    __syncthreads();
    __shared__ float tots;
    if (threadIdx.x == 0) {
        float t = 0.f;
        #pragma unroll
        for (int i = 0; i < 6; i++) t += red[i];
        tots = t;
    }
    __syncthreads();
    float r = rsqrtf(tots / (float)DM_ + EPSF);
    float4 wv = ((const float4*)w)[threadIdx.x];
    float4 o4 = make_float4(v.x * r * wv.x, v.y * r * wv.y, v.z * r * wv.z, v.w * r * wv.w);
    ((float4*)(out + (size_t)row * DM_))[threadIdx.x] = o4;
}

// ---------------- tensor-core GEMM 128x128x16, 3xTF32 split ----------------
// EPI: 0 = store, 1 = bias+gelu, 2 = 0.5*(x+bias)+R, 3 = +R, 4 = +bias
template <int EPI>
__global__ __launch_bounds__(256) void gemm_tc(const float* __restrict__ A,
                                               const float* __restrict__ Bm,
                                               const float* __restrict__ bias,
                                               const float* __restrict__ R,
                                               float* __restrict__ C,
                                               int M, int N, int K) {
    __shared__ float As[16][136];
    __shared__ float Bs[16][136];
    int tid = threadIdx.x;
    int warp = tid >> 5, lane = tid & 31;
    int wm = warp >> 2;
    int wn = warp & 3;
    int g = lane >> 2, tg = lane & 3;

    const float* Ab = A + (size_t)blockIdx.y * 128 * K;
    const float* Bb = Bm + (size_t)blockIdx.x * 128;

    float acc[4][4][4];
    #pragma unroll
    for (int i = 0; i < 4; i++)
        #pragma unroll
        for (int j = 0; j < 4; j++)
            #pragma unroll
            for (int r = 0; r < 4; r++) acc[i][j][r] = 0.f;

    for (int kt = 0; kt < K; kt += 16) {
        #pragma unroll
        for (int p = 0; p < 2; p++) {
            int linear = tid + p * 256;
            int row = linear >> 2;
            int c4 = (linear & 3) << 2;
            float4 v = *(const float4*)(Ab + (size_t)row * K + kt + c4);
            As[c4 + 0][row] = v.x;
            As[c4 + 1][row] = v.y;
            As[c4 + 2][row] = v.z;
            As[c4 + 3][row] = v.w;
        }
        #pragma unroll
        for (int p = 0; p < 2; p++) {
            int linear = tid + p * 256;
            int br = linear >> 5;
            int bc = (linear & 31) << 2;
            float4 v = *(const float4*)(Bb + (size_t)(kt + br) * N + bc);
            *(float4*)&Bs[br][bc] = v;
        }
        __syncthreads();

        #pragma unroll
        for (int ks = 0; ks < 2; ks++) {
            int k0 = ks * 8;
            uint32_t bh[4][2], bl[4][2];
            #pragma unroll
            for (int j = 0; j < 4; j++) {
                int col = wn * 32 + j * 8 + g;
                float b0 = Bs[k0 + tg][col];
                float b1 = Bs[k0 + tg + 4][col];
                split_tf32(b0, bh[j][0], bl[j][0]);
                split_tf32(b1, bh[j][1], bl[j][1]);
            }
            #pragma unroll
            for (int i = 0; i < 4; i++) {
                int r0 = wm * 64 + i * 16 + g;
                float a0 = As[k0 + tg][r0];
                float a1 = As[k0 + tg][r0 + 8];
                float a2 = As[k0 + tg + 4][r0];
                float a3 = As[k0 + tg + 4][r0 + 8];
                uint32_t ah[4], al[4];
                split_tf32(a0, ah[0], al[0]);
                split_tf32(a1, ah[1], al[1]);
                split_tf32(a2, ah[2], al[2]);
                split_tf32(a3, ah[3], al[3]);
                #pragma unroll
                for (int j = 0; j < 4; j++) {
                    mma_tf32(acc[i][j], ah, bl[j]);
                    mma_tf32(acc[i][j], al, bh[j]);
                    mma_tf32(acc[i][j], ah, bh[j]);
                }
            }
        }
        __syncthreads();
    }

    #pragma unroll
    for (int i = 0; i < 4; i++) {
        #pragma unroll
        for (int j = 0; j < 4; j++) {
            size_t row0 = (size_t)blockIdx.y * 128 + wm * 64 + i * 16 + g;
            size_t col0 = (size_t)blockIdx.x * 128 + wn * 32 + j * 8 + 2 * tg;
            #pragma unroll
            for (int h = 0; h < 2; h++) {
                size_t row = row0 + h * 8;
                float v0 = acc[i][j][h * 2 + 0];
                float v1 = acc[i][j][h * 2 + 1];
                if (EPI == 1 || EPI == 2 || EPI == 4) { v0 += bias[col0]; v1 += bias[col0 + 1]; }
                if (EPI == 1) { v0 = gelu_tanh(v0); v1 = gelu_tanh(v1); }
                if (EPI == 2) {
                    v0 = 0.5f * v0 + R[row * N + col0];
                    v1 = 0.5f * v1 + R[row * N + col0 + 1];
                }
                if (EPI == 3) {
                    v0 += R[row * N + col0];
                    v1 += R[row * N + col0 + 1];
                }
                *(float2*)&C[row * N + col0] = make_float2(v0, v1);
            }
        }
    }
}

// ---------------- post-QKV: per-head rmsnorm, RoPE, cache write ----------------
__global__ __launch_bounds__(64) void qkv_post_k(const float* __restrict__ qkv,
                                                 const float* __restrict__ qw,
                                                 const float* __restrict__ kw,
                                                 float* __restrict__ qrot,
                                                 float* __restrict__ krot,
                                                 float* __restrict__ outkv) {
    int row = blockIdx.x;
    int h = blockIdx.y;
    int d = threadIdx.x;
    int b = row / N_, n = row % N_;
    const float* base = qkv + (size_t)row * (3 * DM_) + h * (HD_ * 3);
    float q = base[d * 3 + 0], k = base[d * 3 + 1], v = base[d * 3 + 2];
    float q2 = q * q, k2 = k * k;
    for (int o = 16; o; o >>= 1) {
        q2 += __shfl_xor_sync(0xffffffffu, q2, o);
        k2 += __shfl_xor_sync(0xffffffffu, k2, o);
    }
    __shared__ float red[4];
    if ((d & 31) == 0) { red[d >> 5] = q2; red[2 + (d >> 5)] = k2; }
    __syncthreads();
    float qn = q * rsqrtf((red[0] + red[1]) / (float)HD_ + EPSF) * qw[d];
    float kn = k * rsqrtf((red[2] + red[3]) / (float)HD_ + EPSF) * kw[d];
    __shared__ float sq[64], sk[64];
    sq[d] = qn; sk[d] = kn;
    __syncthreads();
    int pos = CACHE_ + n;
    int i = d & 31;
    float inv = __expf(-(float)i * 0.28782313662425572f);
    float ang = (float)pos * inv;
    float c = cosf(ang), s = sinf(ang);
    float qr, kr;
    if (d < 32) { qr = qn * c - sq[d + 32] * s; kr = kn * c - sk[d + 32] * s; }
    else        { qr = qn * c + sq[d - 32] * s; kr = kn * c + sk[d - 32] * s; }
    qrot[(((size_t)b * N_ + n) * NH_ + h) * HD_ + d] = qr;
    krot[(((size_t)b * KV_ + pos) * NH_ + h) * HD_ + d] = kr;
    size_t cb = (((size_t)b * KV_ + pos) * 2) * DM_ + h * HD_ + d;
    outkv[cb] = kn;
    outkv[cb + DM_] = v;
}

// ---------------- cached KV: copy to output + rope K ----------------
__global__ __launch_bounds__(64) void cache_k(const float* __restrict__ cached,
                                              float* __restrict__ krot,
                                              float* __restrict__ outkv) {
    int row = blockIdx.x;
    int h = blockIdx.y;
    int d = threadIdx.x;
    int b = row / CACHE_, p = row % CACHE_;
    size_t src = (((size_t)b * CACHE_ + p) * 2) * DM_ + h * HD_ + d;
    float k = cached[src], v = cached[src + DM_];
    size_t dst = (((size_t)b * KV_ + p) * 2) * DM_ + h * HD_ + d;
    outkv[dst] = k;
    outkv[dst + DM_] = v;
    __shared__ float sk[64];
    sk[d] = k;
    __syncthreads();
    int i = d & 31;
    float inv = __expf(-(float)i * 0.28782313662425572f);
    float ang = (float)p * inv;
    float c = cosf(ang), s = sinf(ang);
    float kr = (d < 32) ? (k * c - sk[d + 32] * s) : (k * c + sk[d - 32] * s);
    krot[(((size_t)b * KV_ + p) * NH_ + h) * HD_ + d] = kr;
}

// ---------------- tensor-core flash attention ----------------
// 128 threads (4 warps), each warp owns 16 q-rows. KV tile = 64.
// Ks: kv-major stride 68 (QK B-frags conflict-free), Vs stride 72 (PV B-frags
// conflict-free), Ps stride 68 (A-frag loads conflict-free, warp-private).
#define KS_STRIDE 68
#define VS_STRIDE 72
#define PS_STRIDE 68
#define FLASH_SMEM ((64 * KS_STRIDE + 64 * VS_STRIDE + 64 * PS_STRIDE) * 4)
__global__ __launch_bounds__(128) void flash_tc(const float* __restrict__ Q,
                                                const float* __restrict__ Kr,
                                                const float* __restrict__ OUTKV,
                                                float* __restrict__ O) {
    extern __shared__ float sm[];
    float* Ks = sm;                         // [64 kv][68]
    float* Vs = Ks + 64 * KS_STRIDE;        // [64 kv][72]
    float* Ps = Vs + 64 * VS_STRIDE;        // [64 q][68]
    int q0 = blockIdx.x * 64;
    int h = blockIdx.y;
    int b = blockIdx.z;
    int tid = threadIdx.x;
    int warp = tid >> 5, lane = tid & 31;
    int g = lane >> 2, tg = lane & 3;

    // --- load Q fragments (row-major A, m16k8 x8), 3-term split ---
    uint32_t qh[8][4], ql[8][4];
    {
        const float* Qb = Q + (((size_t)(b * N_ + q0 + warp * 16)) * NH_ + h) * HD_;
        #pragma unroll
        for (int kt = 0; kt < 8; kt++) {
            float a0 = Qb[(size_t)g * DM_ + kt * 8 + tg];
            float a1 = Qb[(size_t)(g + 8) * DM_ + kt * 8 + tg];
            float a2 = Qb[(size_t)g * DM_ + kt * 8 + tg + 4];
            float a3 = Qb[(size_t)(g + 8) * DM_ + kt * 8 + tg + 4];
            split_tf32(a0, qh[kt][0], ql[kt][0]);
            split_tf32(a1, qh[kt][1], ql[kt][1]);
            split_tf32(a2, qh[kt][2], ql[kt][2]);
            split_tf32(a3, qh[kt][3], ql[kt][3]);
        }
    }

    const float* Kb = Kr + ((size_t)b * KV_ * NH_ + h) * HD_;                 // + kv*768 + d
    const float* Vb = OUTKV + ((size_t)b * KV_ * 2 + 1) * DM_ + h * HD_;      // + kv*1536 + d

    float m0 = -1e30f, m1 = -1e30f, l0 = 0.f, l1 = 0.f;
    float o[8][4];
    #pragma unroll
    for (int j = 0; j < 8; j++)
        #pragma unroll
        for (int r = 0; r < 4; r++) o[j][r] = 0.f;

    const float SC = 0.125f * 1.44269504088896f;   // 1/sqrt(64) * log2(e)

    for (int t = 0; t < KV_; t += 64) {
        __syncthreads();
        // load K, V tiles (kv-major), float4 coalesced
        for (int e = tid; e < 64 * 16; e += 128) {
            int r = e >> 4, c4 = (e & 15) << 2;
            float4 k4 = *(const float4*)(Kb + (size_t)(t + r) * (NH_ * HD_) + c4);
            *(float4*)&Ks[r * KS_STRIDE + c4] = k4;
            float4 v4 = *(const float4*)(Vb + (size_t)(t + r) * (2 * DM_) + c4);
            *(float4*)&Vs[r * VS_STRIDE + c4] = v4;
        }
        __syncthreads();

        // --- QK^T : s[j] over 8 n-tiles, k-dim = d (8 k-steps), 3-term ---
        float s[8][4];
        #pragma unroll
        for (int j = 0; j < 8; j++)
            #pragma unroll
            for (int r = 0; r < 4; r++) s[j][r] = 0.f;
        #pragma unroll
        for (int kt = 0; kt < 8; kt++) {
            #pragma unroll
            for (int j = 0; j < 8; j++) {
                float b0 = Ks[(j * 8 + g) * KS_STRIDE + kt * 8 + tg];
                float b1 = Ks[(j * 8 + g) * KS_STRIDE + kt * 8 + tg + 4];
                uint32_t bh[2], bl[2];
                split_tf32(b0, bh[0], bl[0]);
                split_tf32(b1, bh[1], bl[1]);
                mma_tf32(s[j], qh[kt], bl);
                mma_tf32(s[j], ql[kt], bh);
                mma_tf32(s[j], qh[kt], bh);
            }
        }

        // --- online softmax (base-2) ---
        float mx0 = -1e30f, mx1 = -1e30f;
        #pragma unroll
        for (int j = 0; j < 8; j++) {
            s[j][0] *= SC; s[j][1] *= SC; s[j][2] *= SC; s[j][3] *= SC;
            mx0 = fmaxf(mx0, fmaxf(s[j][0], s[j][1]));
            mx1 = fmaxf(mx1, fmaxf(s[j][2], s[j][3]));
        }
        mx0 = fmaxf(mx0, __shfl_xor_sync(0xffffffffu, mx0, 1));
        mx0 = fmaxf(mx0, __shfl_xor_sync(0xffffffffu, mx0, 2));
        mx1 = fmaxf(mx1, __shfl_xor_sync(0xffffffffu, mx1, 1));
        mx1 = fmaxf(mx1, __shfl_xor_sync(0xffffffffu, mx1, 2));
        float M0 = fmaxf(m0, mx0), M1 = fmaxf(m1, mx1);
        float a0 = ex2f_(m0 - M0), a1 = ex2f_(m1 - M1);
        m0 = M0; m1 = M1;
        float ls0 = 0.f, ls1 = 0.f;
        int prow0 = (warp * 16 + g) * PS_STRIDE;
        int prow1 = (warp * 16 + g + 8) * PS_STRIDE;
        #pragma unroll
        for (int j = 0; j < 8; j++) {
            float p0 = ex2f_(s[j][0] - M0);
            float p1 = ex2f_(s[j][1] - M0);
            float p2 = ex2f_(s[j][2] - M1);
            float p3 = ex2f_(s[j][3] - M1);
            ls0 += p0 + p1; ls1 += p2 + p3;
            *(float2*)&Ps[prow0 + j * 8 + 2 * tg] = make_float2(p0, p1);
            *(float2*)&Ps[prow1 + j * 8 + 2 * tg] = make_float2(p2, p3);
        }
        ls0 += __shfl_xor_sync(0xffffffffu, ls0, 1);
        ls0 += __shfl_xor_sync(0xffffffffu, ls0, 2);
        ls1 += __shfl_xor_sync(0xffffffffu, ls1, 1);
        ls1 += __shfl_xor_sync(0xffffffffu, ls1, 2);
        l0 = l0 * a0 + ls0;
        l1 = l1 * a1 + ls1;
        #pragma unroll
        for (int j = 0; j < 8; j++) {
            o[j][0] *= a0; o[j][1] *= a0; o[j][2] *= a1; o[j][3] *= a1;
        }
        __syncwarp();

        // --- P·V : k-dim = kv (8 k-steps), n = d (8 tiles), 2-term (V split) ---
        #pragma unroll
        for (int kt = 0; kt < 8; kt++) {
            uint32_t pA[4];
            pA[0] = f2tf32(Ps[prow0 + kt * 8 + tg]);
            pA[1] = f2tf32(Ps[prow1 + kt * 8 + tg]);
            pA[2] = f2tf32(Ps[prow0 + kt * 8 + tg + 4]);
            pA[3] = f2tf32(Ps[prow1 + kt * 8 + tg + 4]);
            #pragma unroll
            for (int j = 0; j < 8; j++) {
                float v0 = Vs[(kt * 8 + tg) * VS_STRIDE + j * 8 + g];
                float v1 = Vs[(kt * 8 + tg + 4) * VS_STRIDE + j * 8 + g];
                uint32_t vh[2], vl[2];
                split_tf32(v0, vh[0], vl[0]);
                split_tf32(v1, vh[1], vl[1]);
                mma_tf32(o[j], pA, vl);
                mma_tf32(o[j], pA, vh);
            }
        }
    }

    // --- epilogue ---
    float il0 = 1.f / l0, il1 = 1.f / l1;
    size_t r0 = (size_t)(b * N_ + q0 + warp * 16 + g) * DM_ + h * HD_;
    size_t r1 = (size_t)(b * N_ + q0 + warp * 16 + g + 8) * DM_ + h * HD_;
    #pragma unroll
    for (int j = 0; j < 8; j++) {
        *(float2*)&O[r0 + j * 8 + 2 * tg] = make_float2(o[j][0] * il0, o[j][1] * il0);
        *(float2*)&O[r1 + j * 8 + 2 * tg] = make_float2(o[j][2] * il1, o[j][3] * il1);
    }
}

// ---------------- GLU: a * sigmoid(b)  (float4) ----------------
__global__ void glu_k(const float* __restrict__ in, float* __restrict__ out) {
    size_t idx = (size_t)blockIdx.x * blockDim.x + threadIdx.x;
    if (idx >= (size_t)ROWS_ * DM_ / 4) return;
    size_t r = idx / (DM_ / 4), c = idx % (DM_ / 4);
    const float4* in4 = (const float4*)in;
    float4 a = in4[r * (2 * DM_ / 4) + c];
    float4 bb = in4[r * (2 * DM_ / 4) + (DM_ / 4) + c];
    float4 o4 = make_float4(a.x * sigmoidf_(bb.x), a.y * sigmoidf_(bb.y),
                            a.z * sigmoidf_(bb.z), a.w * sigmoidf_(bb.w));
    ((float4*)out)[idx] = o4;
}

// ---------------- depthwise conv1d ----------------
__global__ __launch_bounds__(256) void dwconv_k(const float* __restrict__ in,
                                                const float* __restrict__ wt,
                                                const float* __restrict__ bias,
                                                float* __restrict__ out) {
    int row = blockIdx.x;
    int b = row / N_, t = row % N_;
    for (int c = threadIdx.x; c < DM_; c += 256) {
        float acc = bias[c];
        #pragma unroll
        for (int k = 0; k < KSZ_; k++) {
            int t2 = t + k - (KSZ_ / 2);
            if (t2 >= 0 && t2 < N_)
                acc = fmaf(in[((size_t)b * N_ + t2) * DM_ + c], wt[c * KSZ_ + k], acc);
        }
        out[(size_t)row * DM_ + c] = acc;
    }
}

// ---------------- batchnorm stats (coalesced: 32 channels/block) ----------------
__global__ __launch_bounds__(256) void bnstats_k(const float* __restrict__ in,
                                                 float* __restrict__ stats) {
    int tx = threadIdx.x & 31, ty = threadIdx.x >> 5;
    int c = blockIdx.x * 32 + tx;
    double s = 0.0, ss = 0.0;
    for (int r = ty; r < ROWS_; r += 8) {
        float v = in[(size_t)r * DM_ + c];
        s += v; ss += (double)v * v;
    }
    __shared__ double sh_s[8][33], sh_ss[8][33];
    sh_s[ty][tx] = s; sh_ss[ty][tx] = ss;
    __syncthreads();
    if (ty == 0) {
        #pragma unroll
        for (int i = 1; i < 8; i++) { s += sh_s[i][tx]; ss += sh_ss[i][tx]; }
        double mean = s / (double)ROWS_;
        double var = ss / (double)ROWS_ - mean * mean;
        stats[c] = (float)mean;
        stats[DM_ + c] = rsqrtf((float)var + EPSF);
    }
}

// ---------------- batchnorm apply + swish (float4) ----------------
__global__ void bnapply_k(const float* __restrict__ in, const float* __restrict__ stats,
                          const float* __restrict__ g, const float* __restrict__ bb,
                          float* __restrict__ out) {
    size_t idx = (size_t)blockIdx.x * blockDim.x + threadIdx.x;
    if (idx >= (size_t)ROWS_ * DM_ / 4) return;
    int c = (int)(idx % (DM_ / 4)) * 4;
    float4 v = ((const float4*)in)[idx];
    float4 r;
    float y;
    y = (v.x - stats[c + 0]) * stats[DM_ + c + 0] * g[c + 0] + bb[c + 0]; r.x = y * sigmoidf_(y);
    y = (v.y - stats[c + 1]) * stats[DM_ + c + 1] * g[c + 1] + bb[c + 1]; r.y = y * sigmoidf_(y);
    y = (v.z - stats[c + 2]) * stats[DM_ + c + 2] * g[c + 2] + bb[c + 2]; r.z = y * sigmoidf_(y);
    y = (v.w - stats[c + 3]) * stats[DM_ + c + 3] * g[c + 3] + bb[c + 3]; r.w = y * sigmoidf_(y);
    ((float4*)out)[idx] = r;
}

// ---------------- host launcher ----------------
extern "C" void kernel_launch(void* const* d_in, const int* in_sizes, int n_in,
                              void* d_out, int out_size) {
    (void)out_size;
    const float* x = (const float*)d_in[0];
    int ikv = 4;
    for (int i = 1; i < n_in; i++)
        if (in_sizes[i] == 786432) { ikv = i; break; }
    const float* cached_kv = (const float*)d_in[ikv];
    int w = ikv + 1;
    const float* ff1_norm_w = (const float*)d_in[w + 0];
    const float* ff1_w1     = (const float*)d_in[w + 1];
    const float* ff1_b1     = (const float*)d_in[w + 2];
    const float* ff1_w2     = (const float*)d_in[w + 3];
    const float* ff1_b2     = (const float*)d_in[w + 4];
    const float* attn_norm_w= (const float*)d_in[w + 5];
    const float* qkv_w      = (const float*)d_in[w + 6];
    const float* out_w      = (const float*)d_in[w + 7];
    const float* q_norm_w   = (const float*)d_in[w + 8];
    const float* k_norm_w   = (const float*)d_in[w + 9];
    const float* conv_norm_w= (const float*)d_in[w + 10];
    const float* pw1_w      = (const float*)d_in[w + 11];
    const float* pw1_b      = (const float*)d_in[w + 12];
    const float* dw_w       = (const float*)d_in[w + 13];
    const float* dw_b       = (const float*)d_in[w + 14];
    const float* bn_g       = (const float*)d_in[w + 15];
    const float* bn_b       = (const float*)d_in[w + 16];
    const float* pw2_w      = (const float*)d_in[w + 17];
    const float* pw2_b      = (const float*)d_in[w + 18];
    const float* ff2_norm_w = (const float*)d_in[w + 19];
    const float* ff2_w1     = (const float*)d_in[w + 20];
    const float* ff2_b1     = (const float*)d_in[w + 21];
    const float* ff2_w2     = (const float*)d_in[w + 22];
    const float* ff2_b2     = (const float*)d_in[w + 23];
    const float* out_norm_w = (const float*)d_in[w + 24];

    float* out_x  = (float*)d_out;
    float* out_kv = out_x + (size_t)B_ * N_ * DM_;

    float *S0, *S1, *S2, *QR, *KR, *AT, *C1, *C2, *BN;
    cudaGetSymbolAddress((void**)&S0, g_S0);
    cudaGetSymbolAddress((void**)&S1, g_S1);
    cudaGetSymbolAddress((void**)&S2, g_S2);
    cudaGetSymbolAddress((void**)&QR, g_qrot);
    cudaGetSymbolAddress((void**)&KR, g_krot);
    cudaGetSymbolAddress((void**)&AT, g_attn);
    cudaGetSymbolAddress((void**)&C1, g_C1);
    cudaGetSymbolAddress((void**)&C2, g_C2);
    cudaGetSymbolAddress((void**)&BN, g_bn);

    cudaFuncSetAttribute(flash_tc, cudaFuncAttributeMaxDynamicSharedMemorySize, FLASH_SMEM);

    const int EW4_GRID = (int)(((size_t)ROWS_ * DM_ / 4 + 255) / 256);

    // ---- FF1 ----
    rmsnorm_k<<<ROWS_, 192>>>(x, ff1_norm_w, S1);
    gemm_tc<1><<<dim3(FF_ / 128, ROWS_ / 128), 256>>>(S1, ff1_w1, ff1_b1, nullptr, S2, ROWS_, FF_, DM_);
    gemm_tc<2><<<dim3(DM_ / 128, ROWS_ / 128), 256>>>(S2, ff1_w2, ff1_b2, x, S0, ROWS_, DM_, FF_);

    // ---- attention ----
    rmsnorm_k<<<ROWS_, 192>>>(S0, attn_norm_w, S1);
    gemm_tc<0><<<dim3((3 * DM_) / 128, ROWS_ / 128), 256>>>(S1, qkv_w, nullptr, nullptr, S2, ROWS_, 3 * DM_, DM_);
    qkv_post_k<<<dim3(ROWS_, NH_), 64>>>(S2, q_norm_w, k_norm_w, QR, KR, out_kv);
    cache_k<<<dim3(B_ * CACHE_, NH_), 64>>>(cached_kv, KR, out_kv);
    flash_tc<<<dim3(N_ / 64, NH_, B_), 128, FLASH_SMEM>>>(QR, KR, out_kv, AT);
    gemm_tc<3><<<dim3(DM_ / 128, ROWS_ / 128), 256>>>(AT, out_w, nullptr, S0, S0, ROWS_, DM_, DM_);

    // ---- conv module ----
    rmsnorm_k<<<ROWS_, 192>>>(S0, conv_norm_w, S1);
    gemm_tc<4><<<dim3((2 * DM_) / 128, ROWS_ / 128), 256>>>(S1, pw1_w, pw1_b, nullptr, S2, ROWS_, 2 * DM_, DM_);
    glu_k<<<EW4_GRID, 256>>>(S2, C1);
    dwconv_k<<<ROWS_, 256>>>(C1, dw_w, dw_b, C2);
    bnstats_k<<<DM_ / 32, 256>>>(C2, BN);
    bnapply_k<<<EW4_GRID, 256>>>(C2, BN, bn_g, bn_b, C1);
    gemm_tc<4><<<dim3(DM_ / 128, ROWS_ / 128), 256>>>(C1, pw2_w, pw2_b, nullptr, S0, ROWS_, DM_, DM_);

    // ---- FF2 ----
    rmsnorm_k<<<ROWS_, 192>>>(S0, ff2_norm_w, S1);
    gemm_tc<1><<<dim3(FF_ / 128, ROWS_ / 128), 256>>>(S1, ff2_w1, ff2_b1, nullptr, S2, ROWS_, FF_, DM_);
    gemm_tc<2><<<dim3(DM_ / 128, ROWS_ / 128), 256>>>(S2, ff2_w2, ff2_b2, S0, S0, ROWS_, DM_, FF_);

    // ---- final norm ----
    rmsnorm_k<<<ROWS_, 192>>>(S0, out_norm_w, out_x);
}

// round 4
// speedup vs baseline: 2.8082x; 1.3300x over previous
#include <cuda_runtime.h>
#include <cuda_bf16.h>
#include <cstdint>
#include <cmath>

// ---------------- problem constants ----------------
#define B_      2
#define N_      2048
#define CACHE_  512
#define KV_     2560            // CACHE_ + N_
#define DM_     768
#define NH_     12
#define HD_     64
#define FF_     3072
#define KSZ_    31
#define ROWS_   4096            // B_*N_
#define EPSF    1e-5f

// ---------------- scratch ----------------
__device__ float g_S0[(size_t)ROWS_ * DM_];
__device__ float g_S1[(size_t)ROWS_ * DM_];
__device__ float g_S2[(size_t)ROWS_ * FF_];
__device__ float g_qrot[(size_t)ROWS_ * DM_];
__device__ float g_krot[(size_t)B_ * KV_ * DM_];
__device__ float g_attn[(size_t)ROWS_ * DM_];
__device__ float g_C1[(size_t)ROWS_ * DM_];
__device__ float g_C2[(size_t)ROWS_ * DM_];
__device__ float g_bn[2 * DM_];

// ---------------- helpers ----------------
__device__ __forceinline__ float gelu_tanh(float x) {
    float x3 = x * x * x;
    float t  = tanhf(0.7978845608028654f * (x + 0.044715f * x3));
    return 0.5f * x * (1.0f + t);
}
__device__ __forceinline__ float sigmoidf_(float x) {
    return 1.0f / (1.0f + __expf(-x));
}
__device__ __forceinline__ float ex2f_(float x) {
    float y;
    asm("ex2.approx.f32 %0, %1;" : "=f"(y) : "f"(x));
    return y;
}
// split (x,y) into packed bf16 hi pair + bf16 lo (residual) pair
__device__ __forceinline__ void split2(float x, float y, uint32_t& hi, uint32_t& lo) {
    __nv_bfloat162 h = __floats2bfloat162_rn(x, y);
    float rx = x - __bfloat162float(h.x);
    float ry = y - __bfloat162float(h.y);
    __nv_bfloat162 l = __floats2bfloat162_rn(rx, ry);
    hi = *reinterpret_cast<uint32_t*>(&h);
    lo = *reinterpret_cast<uint32_t*>(&l);
}
__device__ __forceinline__ void mma_bf(float (&c)[4], const uint32_t (&a)[4], const uint32_t (&b)[2]) {
    asm volatile(
        "mma.sync.aligned.m16n8k16.row.col.f32.bf16.bf16.f32 "
        "{%0,%1,%2,%3}, {%4,%5,%6,%7}, {%8,%9}, {%0,%1,%2,%3};\n"
        : "+f"(c[0]), "+f"(c[1]), "+f"(c[2]), "+f"(c[3])
        : "r"(a[0]), "r"(a[1]), "r"(a[2]), "r"(a[3]), "r"(b[0]), "r"(b[1]));
}

// ---------------- RMSNorm over DM_=768 (float4) ----------------
__global__ __launch_bounds__(192) void rmsnorm_k(const float* __restrict__ in,
                                                 const float* __restrict__ w,
                                                 float* __restrict__ out) {
    int row = blockIdx.x;
    const float4* p = (const float4*)(in + (size_t)row * DM_);
    float4 v = p[threadIdx.x];
    float ss = v.x * v.x + v.y * v.y + v.z * v.z + v.w * v.w;
    for (int o = 16; o; o >>= 1) ss += __shfl_xor_sync(0xffffffffu, ss, o);
    __shared__ float red[6];
    if ((threadIdx.x & 31) == 0) red[threadIdx.x >> 5] = ss;
    __syncthreads();
    __shared__ float tots;
    if (threadIdx.x == 0) {
        float t = 0.f;
        #pragma unroll
        for (int i = 0; i < 6; i++) t += red[i];
        tots = t;
    }
    __syncthreads();
    float r = rsqrtf(tots / (float)DM_ + EPSF);
    float4 wv = ((const float4*)w)[threadIdx.x];
    float4 o4 = make_float4(v.x * r * wv.x, v.y * r * wv.y, v.z * r * wv.z, v.w * r * wv.w);
    ((float4*)(out + (size_t)row * DM_))[threadIdx.x] = o4;
}

// ---------------- BF16 tensor-core GEMM 128x128x16, 2-term split, 3 products --
// EPI: 0 = store, 1 = bias+gelu, 2 = 0.5*(x+bias)+R, 3 = +R, 4 = +bias
template <int EPI>
__global__ __launch_bounds__(256) void gemm_bf(const float* __restrict__ A,
                                               const float* __restrict__ Bm,
                                               const float* __restrict__ bias,
                                               const float* __restrict__ R,
                                               float* __restrict__ C,
                                               int M, int N, int K) {
    __shared__ uint32_t Ah[128][9], Al[128][9];   // [m][k-pair], packed bf16x2
    __shared__ uint32_t Bh[128][9], Bl[128][9];   // [n][k-pair]
    int tid = threadIdx.x;
    int warp = tid >> 5, lane = tid & 31;
    int wm = warp >> 2, wn = warp & 3;
    int g = lane >> 2, tg = lane & 3;
    const float* Ab = A + (size_t)blockIdx.y * 128 * K;
    const float* Bb = Bm + (size_t)blockIdx.x * 128;

    float acc[4][4][4];
    #pragma unroll
    for (int i = 0; i < 4; i++)
        #pragma unroll
        for (int j = 0; j < 4; j++)
            #pragma unroll
            for (int r = 0; r < 4; r++) acc[i][j][r] = 0.f;

    int arow = tid >> 2, ac = tid & 3;     // A: row (+64), float4 col idx
    int bn4 = tid >> 3, bkp = tid & 7;     // B: n-float4 idx 0..31, k-pair 0..7

    for (int kt = 0; kt < K; kt += 16) {
        #pragma unroll
        for (int p = 0; p < 2; p++) {
            int row = arow + 64 * p;
            float4 v = *(const float4*)(Ab + (size_t)row * K + kt + 4 * ac);
            split2(v.x, v.y, Ah[row][2 * ac], Al[row][2 * ac]);
            split2(v.z, v.w, Ah[row][2 * ac + 1], Al[row][2 * ac + 1]);
        }
        {
            const float* p0 = Bb + (size_t)(kt + 2 * bkp) * N + 4 * bn4;
            float4 r0 = *(const float4*)p0;
            float4 r1 = *(const float4*)(p0 + N);
            split2(r0.x, r1.x, Bh[4 * bn4 + 0][bkp], Bl[4 * bn4 + 0][bkp]);
            split2(r0.y, r1.y, Bh[4 * bn4 + 1][bkp], Bl[4 * bn4 + 1][bkp]);
            split2(r0.z, r1.z, Bh[4 * bn4 + 2][bkp], Bl[4 * bn4 + 2][bkp]);
            split2(r0.w, r1.w, Bh[4 * bn4 + 3][bkp], Bl[4 * bn4 + 3][bkp]);
        }
        __syncthreads();

        uint32_t bh[4][2], bl[4][2];
        #pragma unroll
        for (int j = 0; j < 4; j++) {
            int col = wn * 32 + j * 8 + g;
            bh[j][0] = Bh[col][tg]; bh[j][1] = Bh[col][tg + 4];
            bl[j][0] = Bl[col][tg]; bl[j][1] = Bl[col][tg + 4];
        }
        #pragma unroll
        for (int i = 0; i < 4; i++) {
            int r = wm * 64 + i * 16 + g;
            uint32_t ah[4] = {Ah[r][tg], Ah[r + 8][tg], Ah[r][tg + 4], Ah[r + 8][tg + 4]};
            uint32_t al[4] = {Al[r][tg], Al[r + 8][tg], Al[r][tg + 4], Al[r + 8][tg + 4]};
            #pragma unroll
            for (int j = 0; j < 4; j++) {
                mma_bf(acc[i][j], ah, bl[j]);
                mma_bf(acc[i][j], al, bh[j]);
                mma_bf(acc[i][j], ah, bh[j]);
            }
        }
        __syncthreads();
    }

    #pragma unroll
    for (int i = 0; i < 4; i++) {
        #pragma unroll
        for (int j = 0; j < 4; j++) {
            size_t row0 = (size_t)blockIdx.y * 128 + wm * 64 + i * 16 + g;
            size_t col0 = (size_t)blockIdx.x * 128 + wn * 32 + j * 8 + 2 * tg;
            #pragma unroll
            for (int h = 0; h < 2; h++) {
                size_t row = row0 + h * 8;
                float v0 = acc[i][j][h * 2 + 0];
                float v1 = acc[i][j][h * 2 + 1];
                if (EPI == 1 || EPI == 2 || EPI == 4) { v0 += bias[col0]; v1 += bias[col0 + 1]; }
                if (EPI == 1) { v0 = gelu_tanh(v0); v1 = gelu_tanh(v1); }
                if (EPI == 2) {
                    v0 = 0.5f * v0 + R[row * N + col0];
                    v1 = 0.5f * v1 + R[row * N + col0 + 1];
                }
                if (EPI == 3) {
                    v0 += R[row * N + col0];
                    v1 += R[row * N + col0 + 1];
                }
                *(float2*)&C[row * N + col0] = make_float2(v0, v1);
            }
        }
    }
}

// ---------------- post-QKV: per-head rmsnorm, RoPE, cache write ----------------
__global__ __launch_bounds__(64) void qkv_post_k(const float* __restrict__ qkv,
                                                 const float* __restrict__ qw,
                                                 const float* __restrict__ kw,
                                                 float* __restrict__ qrot,
                                                 float* __restrict__ krot,
                                                 float* __restrict__ outkv) {
    int row = blockIdx.x;
    int h = blockIdx.y;
    int d = threadIdx.x;
    int b = row / N_, n = row % N_;
    const float* base = qkv + (size_t)row * (3 * DM_) + h * (HD_ * 3);
    float q = base[d * 3 + 0], k = base[d * 3 + 1], v = base[d * 3 + 2];
    float q2 = q * q, k2 = k * k;
    for (int o = 16; o; o >>= 1) {
        q2 += __shfl_xor_sync(0xffffffffu, q2, o);
        k2 += __shfl_xor_sync(0xffffffffu, k2, o);
    }
    __shared__ float red[4];
    if ((d & 31) == 0) { red[d >> 5] = q2; red[2 + (d >> 5)] = k2; }
    __syncthreads();
    float qn = q * rsqrtf((red[0] + red[1]) / (float)HD_ + EPSF) * qw[d];
    float kn = k * rsqrtf((red[2] + red[3]) / (float)HD_ + EPSF) * kw[d];
    __shared__ float sq[64], sk[64];
    sq[d] = qn; sk[d] = kn;
    __syncthreads();
    int pos = CACHE_ + n;
    int i = d & 31;
    float inv = __expf(-(float)i * 0.28782313662425572f);
    float ang = (float)pos * inv;
    float c = cosf(ang), s = sinf(ang);
    float qr, kr;
    if (d < 32) { qr = qn * c - sq[d + 32] * s; kr = kn * c - sk[d + 32] * s; }
    else        { qr = qn * c + sq[d - 32] * s; kr = kn * c + sk[d - 32] * s; }
    qrot[(((size_t)b * N_ + n) * NH_ + h) * HD_ + d] = qr;
    krot[(((size_t)b * KV_ + pos) * NH_ + h) * HD_ + d] = kr;
    size_t cb = (((size_t)b * KV_ + pos) * 2) * DM_ + h * HD_ + d;
    outkv[cb] = kn;
    outkv[cb + DM_] = v;
}

// ---------------- cached KV: copy to output + rope K ----------------
__global__ __launch_bounds__(64) void cache_k(const float* __restrict__ cached,
                                              float* __restrict__ krot,
                                              float* __restrict__ outkv) {
    int row = blockIdx.x;
    int h = blockIdx.y;
    int d = threadIdx.x;
    int b = row / CACHE_, p = row % CACHE_;
    size_t src = (((size_t)b * CACHE_ + p) * 2) * DM_ + h * HD_ + d;
    float k = cached[src], v = cached[src + DM_];
    size_t dst = (((size_t)b * KV_ + p) * 2) * DM_ + h * HD_ + d;
    outkv[dst] = k;
    outkv[dst + DM_] = v;
    __shared__ float sk[64];
    sk[d] = k;
    __syncthreads();
    int i = d & 31;
    float inv = __expf(-(float)i * 0.28782313662425572f);
    float ang = (float)p * inv;
    float c = cosf(ang), s = sinf(ang);
    float kr = (d < 32) ? (k * c - sk[d + 32] * s) : (k * c + sk[d - 32] * s);
    krot[(((size_t)b * KV_ + p) * NH_ + h) * HD_ + d] = kr;
}

// ---------------- BF16 tensor-core flash attention ----------------
// 128 threads (4 warps), each warp owns 16 q-rows. KV tile = 64.
// K split once into Kh/Kl [kv][d-pair] (stride 34), V into Vh/Vl [d][kv-pair]
// (stride 35). P fed to PV directly from score registers (A-frag == C-frag).
#define KST 34
#define VST 35
__global__ __launch_bounds__(128) void flash_bf(const float* __restrict__ Q,
                                                const float* __restrict__ Kr,
                                                const float* __restrict__ OUTKV,
                                                float* __restrict__ O) {
    __shared__ uint32_t Kh[64][KST], Kl[64][KST];
    __shared__ uint32_t Vh[64][VST], Vl[64][VST];
    int q0 = blockIdx.x * 64;
    int h = blockIdx.y;
    int b = blockIdx.z;
    int tid = threadIdx.x;
    int warp = tid >> 5, lane = tid & 31;
    int g = lane >> 2, tg = lane & 3;

    // --- Q fragments (2-term bf16 split), 4 k16-steps over d=64 ---
    uint32_t qh[4][4], ql[4][4];
    {
        const float* Qb = Q + (((size_t)(b * N_ + q0 + warp * 16)) * NH_ + h) * HD_;
        #pragma unroll
        for (int kt = 0; kt < 4; kt++) {
            float2 x0 = *(const float2*)(Qb + (size_t)g * DM_ + 16 * kt + 2 * tg);
            float2 x1 = *(const float2*)(Qb + (size_t)(g + 8) * DM_ + 16 * kt + 2 * tg);
            float2 x2 = *(const float2*)(Qb + (size_t)g * DM_ + 16 * kt + 2 * tg + 8);
            float2 x3 = *(const float2*)(Qb + (size_t)(g + 8) * DM_ + 16 * kt + 2 * tg + 8);
            split2(x0.x, x0.y, qh[kt][0], ql[kt][0]);
            split2(x1.x, x1.y, qh[kt][1], ql[kt][1]);
            split2(x2.x, x2.y, qh[kt][2], ql[kt][2]);
            split2(x3.x, x3.y, qh[kt][3], ql[kt][3]);
        }
    }

    const float* Kb = Kr + ((size_t)b * KV_ * NH_ + h) * HD_;              // + kv*768 + d
    const float* Vb = OUTKV + ((size_t)b * KV_ * 2 + 1) * DM_ + h * HD_;   // + kv*1536 + d

    float m0 = -1e30f, m1 = -1e30f, l0 = 0.f, l1 = 0.f;
    float o[8][4];
    #pragma unroll
    for (int j = 0; j < 8; j++)
        #pragma unroll
        for (int r = 0; r < 4; r++) o[j][r] = 0.f;

    const float SC = 0.125f * 1.44269504088896f;   // 1/sqrt(64) * log2(e)

    for (int t = 0; t < KV_; t += 64) {
        __syncthreads();
        // K tile: [kv][d] -> packed pairs along d
        for (int e = tid; e < 64 * 16; e += 128) {
            int r = e >> 4, c4 = e & 15;
            float4 k4 = *(const float4*)(Kb + (size_t)(t + r) * (NH_ * HD_) + 4 * c4);
            split2(k4.x, k4.y, Kh[r][2 * c4], Kl[r][2 * c4]);
            split2(k4.z, k4.w, Kh[r][2 * c4 + 1], Kl[r][2 * c4 + 1]);
        }
        // V tile: pack pairs along kv (transposed store)
        for (int e = tid; e < 32 * 16; e += 128) {
            int kvp = e >> 4, c4 = e & 15;
            const float* vp = Vb + (size_t)(t + 2 * kvp) * (2 * DM_) + 4 * c4;
            float4 v0 = *(const float4*)vp;
            float4 v1 = *(const float4*)(vp + 2 * DM_);
            split2(v0.x, v1.x, Vh[4 * c4 + 0][kvp], Vl[4 * c4 + 0][kvp]);
            split2(v0.y, v1.y, Vh[4 * c4 + 1][kvp], Vl[4 * c4 + 1][kvp]);
            split2(v0.z, v1.z, Vh[4 * c4 + 2][kvp], Vl[4 * c4 + 2][kvp]);
            split2(v0.w, v1.w, Vh[4 * c4 + 3][kvp], Vl[4 * c4 + 3][kvp]);
        }
        __syncthreads();

        // --- QK^T : 8 kv-tiles x 4 k16-steps, 3 products ---
        float s[8][4];
        #pragma unroll
        for (int j = 0; j < 8; j++)
            #pragma unroll
            for (int r = 0; r < 4; r++) s[j][r] = 0.f;
        #pragma unroll
        for (int kt = 0; kt < 4; kt++) {
            #pragma unroll
            for (int j = 0; j < 8; j++) {
                int kv = j * 8 + g;
                uint32_t kbh[2] = {Kh[kv][8 * kt + tg], Kh[kv][8 * kt + tg + 4]};
                uint32_t kbl[2] = {Kl[kv][8 * kt + tg], Kl[kv][8 * kt + tg + 4]};
                mma_bf(s[j], qh[kt], kbl);
                mma_bf(s[j], ql[kt], kbh);
                mma_bf(s[j], qh[kt], kbh);
            }
        }

        // --- online softmax (base-2) ---
        float mx0 = -1e30f, mx1 = -1e30f;
        #pragma unroll
        for (int j = 0; j < 8; j++) {
            s[j][0] *= SC; s[j][1] *= SC; s[j][2] *= SC; s[j][3] *= SC;
            mx0 = fmaxf(mx0, fmaxf(s[j][0], s[j][1]));
            mx1 = fmaxf(mx1, fmaxf(s[j][2], s[j][3]));
        }
        mx0 = fmaxf(mx0, __shfl_xor_sync(0xffffffffu, mx0, 1));
        mx0 = fmaxf(mx0, __shfl_xor_sync(0xffffffffu, mx0, 2));
        mx1 = fmaxf(mx1, __shfl_xor_sync(0xffffffffu, mx1, 1));
        mx1 = fmaxf(mx1, __shfl_xor_sync(0xffffffffu, mx1, 2));
        float M0 = fmaxf(m0, mx0), M1 = fmaxf(m1, mx1);
        float a0 = ex2f_(m0 - M0), a1 = ex2f_(m1 - M1);
        m0 = M0; m1 = M1;
        float ls0 = 0.f, ls1 = 0.f;
        #pragma unroll
        for (int j = 0; j < 8; j++) {
            s[j][0] = ex2f_(s[j][0] - M0);
            s[j][1] = ex2f_(s[j][1] - M0);
            s[j][2] = ex2f_(s[j][2] - M1);
            s[j][3] = ex2f_(s[j][3] - M1);
            ls0 += s[j][0] + s[j][1];
            ls1 += s[j][2] + s[j][3];
        }
        ls0 += __shfl_xor_sync(0xffffffffu, ls0, 1);
        ls0 += __shfl_xor_sync(0xffffffffu, ls0, 2);
        ls1 += __shfl_xor_sync(0xffffffffu, ls1, 1);
        ls1 += __shfl_xor_sync(0xffffffffu, ls1, 2);
        l0 = l0 * a0 + ls0;
        l1 = l1 * a1 + ls1;
        #pragma unroll
        for (int j = 0; j < 8; j++) {
            o[j][0] *= a0; o[j][1] *= a0; o[j][2] *= a1; o[j][3] *= a1;
        }

        // --- P·V : P from registers (A-frag == C-frag layout), 3 products ---
        #pragma unroll
        for (int kt = 0; kt < 4; kt++) {
            uint32_t ph[4], pl[4];
            split2(s[2 * kt][0], s[2 * kt][1], ph[0], pl[0]);
            split2(s[2 * kt][2], s[2 * kt][3], ph[1], pl[1]);
            split2(s[2 * kt + 1][0], s[2 * kt + 1][1], ph[2], pl[2]);
            split2(s[2 * kt + 1][2], s[2 * kt + 1][3], ph[3], pl[3]);
            #pragma unroll
            for (int j = 0; j < 8; j++) {
                int d = j * 8 + g;
                uint32_t vbh[2] = {Vh[d][8 * kt + tg], Vh[d][8 * kt + tg + 4]};
                uint32_t vbl[2] = {Vl[d][8 * kt + tg], Vl[d][8 * kt + tg + 4]};
                mma_bf(o[j], ph, vbl);
                mma_bf(o[j], pl, vbh);
                mma_bf(o[j], ph, vbh);
            }
        }
    }

    // --- epilogue ---
    float il0 = 1.f / l0, il1 = 1.f / l1;
    size_t r0 = (size_t)(b * N_ + q0 + warp * 16 + g) * DM_ + h * HD_;
    size_t r1 = (size_t)(b * N_ + q0 + warp * 16 + g + 8) * DM_ + h * HD_;
    #pragma unroll
    for (int j = 0; j < 8; j++) {
        *(float2*)&O[r0 + j * 8 + 2 * tg] = make_float2(o[j][0] * il0, o[j][1] * il0);
        *(float2*)&O[r1 + j * 8 + 2 * tg] = make_float2(o[j][2] * il1, o[j][3] * il1);
    }
}

// ---------------- GLU: a * sigmoid(b)  (float4) ----------------
__global__ void glu_k(const float* __restrict__ in, float* __restrict__ out) {
    size_t idx = (size_t)blockIdx.x * blockDim.x + threadIdx.x;
    if (idx >= (size_t)ROWS_ * DM_ / 4) return;
    size_t r = idx / (DM_ / 4), c = idx % (DM_ / 4);
    const float4* in4 = (const float4*)in;
    float4 a = in4[r * (2 * DM_ / 4) + c];
    float4 bb = in4[r * (2 * DM_ / 4) + (DM_ / 4) + c];
    float4 o4 = make_float4(a.x * sigmoidf_(bb.x), a.y * sigmoidf_(bb.y),
                            a.z * sigmoidf_(bb.z), a.w * sigmoidf_(bb.w));
    ((float4*)out)[idx] = o4;
}

// ---------------- depthwise conv1d ----------------
__global__ __launch_bounds__(256) void dwconv_k(const float* __restrict__ in,
                                                const float* __restrict__ wt,
                                                const float* __restrict__ bias,
                                                float* __restrict__ out) {
    int row = blockIdx.x;
    int b = row / N_, t = row % N_;
    for (int c = threadIdx.x; c < DM_; c += 256) {
        float acc = bias[c];
        #pragma unroll
        for (int k = 0; k < KSZ_; k++) {
            int t2 = t + k - (KSZ_ / 2);
            if (t2 >= 0 && t2 < N_)
                acc = fmaf(in[((size_t)b * N_ + t2) * DM_ + c], wt[c * KSZ_ + k], acc);
        }
        out[(size_t)row * DM_ + c] = acc;
    }
}

// ---------------- batchnorm stats (coalesced: 32 channels/block) ----------------
__global__ __launch_bounds__(256) void bnstats_k(const float* __restrict__ in,
                                                 float* __restrict__ stats) {
    int tx = threadIdx.x & 31, ty = threadIdx.x >> 5;
    int c = blockIdx.x * 32 + tx;
    double s = 0.0, ss = 0.0;
    for (int r = ty; r < ROWS_; r += 8) {
        float v = in[(size_t)r * DM_ + c];
        s += v; ss += (double)v * v;
    }
    __shared__ double sh_s[8][33], sh_ss[8][33];
    sh_s[ty][tx] = s; sh_ss[ty][tx] = ss;
    __syncthreads();
    if (ty == 0) {
        #pragma unroll
        for (int i = 1; i < 8; i++) { s += sh_s[i][tx]; ss += sh_ss[i][tx]; }
        double mean = s / (double)ROWS_;
        double var = ss / (double)ROWS_ - mean * mean;
        stats[c] = (float)mean;
        stats[DM_ + c] = rsqrtf((float)var + EPSF);
    }
}

// ---------------- batchnorm apply + swish (float4) ----------------
__global__ void bnapply_k(const float* __restrict__ in, const float* __restrict__ stats,
                          const float* __restrict__ g, const float* __restrict__ bb,
                          float* __restrict__ out) {
    size_t idx = (size_t)blockIdx.x * blockDim.x + threadIdx.x;
    if (idx >= (size_t)ROWS_ * DM_ / 4) return;
    int c = (int)(idx % (DM_ / 4)) * 4;
    float4 v = ((const float4*)in)[idx];
    float4 r;
    float y;
    y = (v.x - stats[c + 0]) * stats[DM_ + c + 0] * g[c + 0] + bb[c + 0]; r.x = y * sigmoidf_(y);
    y = (v.y - stats[c + 1]) * stats[DM_ + c + 1] * g[c + 1] + bb[c + 1]; r.y = y * sigmoidf_(y);
    y = (v.z - stats[c + 2]) * stats[DM_ + c + 2] * g[c + 2] + bb[c + 2]; r.z = y * sigmoidf_(y);
    y = (v.w - stats[c + 3]) * stats[DM_ + c + 3] * g[c + 3] + bb[c + 3]; r.w = y * sigmoidf_(y);
    ((float4*)out)[idx] = r;
}

// ---------------- host launcher ----------------
extern "C" void kernel_launch(void* const* d_in, const int* in_sizes, int n_in,
                              void* d_out, int out_size) {
    (void)out_size;
    const float* x = (const float*)d_in[0];
    int ikv = 4;
    for (int i = 1; i < n_in; i++)
        if (in_sizes[i] == 786432) { ikv = i; break; }
    const float* cached_kv = (const float*)d_in[ikv];
    int w = ikv + 1;
    const float* ff1_norm_w = (const float*)d_in[w + 0];
    const float* ff1_w1     = (const float*)d_in[w + 1];
    const float* ff1_b1     = (const float*)d_in[w + 2];
    const float* ff1_w2     = (const float*)d_in[w + 3];
    const float* ff1_b2     = (const float*)d_in[w + 4];
    const float* attn_norm_w= (const float*)d_in[w + 5];
    const float* qkv_w      = (const float*)d_in[w + 6];
    const float* out_w      = (const float*)d_in[w + 7];
    const float* q_norm_w   = (const float*)d_in[w + 8];
    const float* k_norm_w   = (const float*)d_in[w + 9];
    const float* conv_norm_w= (const float*)d_in[w + 10];
    const float* pw1_w      = (const float*)d_in[w + 11];
    const float* pw1_b      = (const float*)d_in[w + 12];
    const float* dw_w       = (const float*)d_in[w + 13];
    const float* dw_b       = (const float*)d_in[w + 14];
    const float* bn_g       = (const float*)d_in[w + 15];
    const float* bn_b       = (const float*)d_in[w + 16];
    const float* pw2_w      = (const float*)d_in[w + 17];
    const float* pw2_b      = (const float*)d_in[w + 18];
    const float* ff2_norm_w = (const float*)d_in[w + 19];
    const float* ff2_w1     = (const float*)d_in[w + 20];
    const float* ff2_b1     = (const float*)d_in[w + 21];
    const float* ff2_w2     = (const float*)d_in[w + 22];
    const float* ff2_b2     = (const float*)d_in[w + 23];
    const float* out_norm_w = (const float*)d_in[w + 24];

    float* out_x  = (float*)d_out;
    float* out_kv = out_x + (size_t)B_ * N_ * DM_;

    float *S0, *S1, *S2, *QR, *KR, *AT, *C1, *C2, *BN;
    cudaGetSymbolAddress((void**)&S0, g_S0);
    cudaGetSymbolAddress((void**)&S1, g_S1);
    cudaGetSymbolAddress((void**)&S2, g_S2);
    cudaGetSymbolAddress((void**)&QR, g_qrot);
    cudaGetSymbolAddress((void**)&KR, g_krot);
    cudaGetSymbolAddress((void**)&AT, g_attn);
    cudaGetSymbolAddress((void**)&C1, g_C1);
    cudaGetSymbolAddress((void**)&C2, g_C2);
    cudaGetSymbolAddress((void**)&BN, g_bn);

    const int EW4_GRID = (int)(((size_t)ROWS_ * DM_ / 4 + 255) / 256);

    // ---- FF1 ----
    rmsnorm_k<<<ROWS_, 192>>>(x, ff1_norm_w, S1);
    gemm_bf<1><<<dim3(FF_ / 128, ROWS_ / 128), 256>>>(S1, ff1_w1, ff1_b1, nullptr, S2, ROWS_, FF_, DM_);
    gemm_bf<2><<<dim3(DM_ / 128, ROWS_ / 128), 256>>>(S2, ff1_w2, ff1_b2, x, S0, ROWS_, DM_, FF_);

    // ---- attention ----
    rmsnorm_k<<<ROWS_, 192>>>(S0, attn_norm_w, S1);
    gemm_bf<0><<<dim3((3 * DM_) / 128, ROWS_ / 128), 256>>>(S1, qkv_w, nullptr, nullptr, S2, ROWS_, 3 * DM_, DM_);
    qkv_post_k<<<dim3(ROWS_, NH_), 64>>>(S2, q_norm_w, k_norm_w, QR, KR, out_kv);
    cache_k<<<dim3(B_ * CACHE_, NH_), 64>>>(cached_kv, KR, out_kv);
    flash_bf<<<dim3(N_ / 64, NH_, B_), 128>>>(QR, KR, out_kv, AT);
    gemm_bf<3><<<dim3(DM_ / 128, ROWS_ / 128), 256>>>(AT, out_w, nullptr, S0, S0, ROWS_, DM_, DM_);

    // ---- conv module ----
    rmsnorm_k<<<ROWS_, 192>>>(S0, conv_norm_w, S1);
    gemm_bf<4><<<dim3((2 * DM_) / 128, ROWS_ / 128), 256>>>(S1, pw1_w, pw1_b, nullptr, S2, ROWS_, 2 * DM_, DM_);
    glu_k<<<EW4_GRID, 256>>>(S2, C1);
    dwconv_k<<<ROWS_, 256>>>(C1, dw_w, dw_b, C2);
    bnstats_k<<<DM_ / 32, 256>>>(C2, BN);
    bnapply_k<<<EW4_GRID, 256>>>(C2, BN, bn_g, bn_b, C1);
    gemm_bf<4><<<dim3(DM_ / 128, ROWS_ / 128), 256>>>(C1, pw2_w, pw2_b, nullptr, S0, ROWS_, DM_, DM_);

    // ---- FF2 ----
    rmsnorm_k<<<ROWS_, 192>>>(S0, ff2_norm_w, S1);
    gemm_bf<1><<<dim3(FF_ / 128, ROWS_ / 128), 256>>>(S1, ff2_w1, ff2_b1, nullptr, S2, ROWS_, FF_, DM_);
    gemm_bf<2><<<dim3(DM_ / 128, ROWS_ / 128), 256>>>(S2, ff2_w2, ff2_b2, S0, S0, ROWS_, DM_, FF_);

    // ---- final norm ----
    rmsnorm_k<<<ROWS_, 192>>>(S0, out_norm_w, out_x);
}

// round 8
// speedup vs baseline: 3.1988x; 1.1391x over previous
#include <cuda_runtime.h>
#include <cuda_bf16.h>
#include <cstdint>
#include <cmath>

// ---------------- problem constants ----------------
#define B_      2
#define N_      2048
#define CACHE_  512
#define KV_     2560            // CACHE_ + N_
#define DM_     768
#define NH_     12
#define HD_     64
#define FF_     3072
#define KSZ_    31
#define ROWS_   4096            // B_*N_
#define EPSF    1e-5f
#define DP_     (DM_ / 2)       // 384 pairs per DM row
#define FFP_    (FF_ / 2)       // 1536

// ---------------- scratch ----------------
__device__ float    g_S0[(size_t)ROWS_ * DM_];        // residual stream
__device__ float    g_S2f[(size_t)ROWS_ * 2304];      // qkv / pw1 float out
__device__ uint32_t g_S1h[(size_t)ROWS_ * DP_];       // rmsnorm split
__device__ uint32_t g_S1l[(size_t)ROWS_ * DP_];
__device__ uint32_t g_S2h[(size_t)ROWS_ * FFP_];      // gelu split
__device__ uint32_t g_S2l[(size_t)ROWS_ * FFP_];
__device__ uint32_t g_ATh[(size_t)ROWS_ * DP_];       // attention out split
__device__ uint32_t g_ATl[(size_t)ROWS_ * DP_];
__device__ uint32_t g_C1h[(size_t)ROWS_ * DP_];       // bnapply split
__device__ uint32_t g_C1l[(size_t)ROWS_ * DP_];
__device__ float    g_QR[(size_t)ROWS_ * DM_];        // roped Q float
__device__ uint32_t g_KRh[(size_t)B_ * NH_ * KV_ * 32]; // roped K split [b][h][kv][dp]
__device__ uint32_t g_KRl[(size_t)B_ * NH_ * KV_ * 32];
__device__ uint32_t g_Vh[(size_t)B_ * NH_ * HD_ * (KV_ / 2)]; // V split T [b][h][d][kvp]
__device__ uint32_t g_Vl[(size_t)B_ * NH_ * HD_ * (KV_ / 2)];
__device__ float    g_C1f[(size_t)ROWS_ * DM_];       // glu out
__device__ float    g_C2f[(size_t)ROWS_ * DM_];       // dwconv out
__device__ float    g_bn[2 * DM_];
__device__ uint32_t g_Wh[6782976];                    // all weights split, hi
__device__ uint32_t g_Wl[6782976];                    // lo

// ---------------- helpers ----------------
__device__ __forceinline__ float gelu_tanh(float x) {
    float x3 = x * x * x;
    float t  = tanhf(0.7978845608028654f * (x + 0.044715f * x3));
    return 0.5f * x * (1.0f + t);
}
__device__ __forceinline__ float sigmoidf_(float x) {
    return 1.0f / (1.0f + __expf(-x));
}
__device__ __forceinline__ float ex2f_(float x) {
    float y;
    asm("ex2.approx.f32 %0, %1;" : "=f"(y) : "f"(x));
    return y;
}
__device__ __forceinline__ void split2(float x, float y, uint32_t& hi, uint32_t& lo) {
    __nv_bfloat162 h = __floats2bfloat162_rn(x, y);
    float rx = x - __bfloat162float(h.x);
    float ry = y - __bfloat162float(h.y);
    __nv_bfloat162 l = __floats2bfloat162_rn(rx, ry);
    hi = *reinterpret_cast<uint32_t*>(&h);
    lo = *reinterpret_cast<uint32_t*>(&l);
}
__device__ __forceinline__ void mma_bf(float (&c)[4], const uint32_t (&a)[4], const uint32_t (&b)[2]) {
    asm volatile(
        "mma.sync.aligned.m16n8k16.row.col.f32.bf16.bf16.f32 "
        "{%0,%1,%2,%3}, {%4,%5,%6,%7}, {%8,%9}, {%0,%1,%2,%3};\n"
        : "+f"(c[0]), "+f"(c[1]), "+f"(c[2]), "+f"(c[3])
        : "r"(a[0]), "r"(a[1]), "r"(a[2]), "r"(a[3]), "r"(b[0]), "r"(b[1]));
}

// ---------------- weight split: W[K][N] -> Wh/Wl [N][K/2] packed ----------------
__global__ __launch_bounds__(256) void wsplit_k(const float* __restrict__ W,
                                                uint32_t* __restrict__ Wh,
                                                uint32_t* __restrict__ Wl,
                                                int K, int N) {
    __shared__ float sm[64][33];
    int k0 = blockIdx.x * 64, n0 = blockIdx.y * 32;
    int tid = threadIdx.x;
    #pragma unroll
    for (int j = 0; j < 8; j++) {
        int i = tid + j * 256;
        int kl = i >> 5, nl = i & 31;
        sm[kl][nl] = W[(size_t)(k0 + kl) * N + n0 + nl];
    }
    __syncthreads();
    int Kp = K >> 1;
    #pragma unroll
    for (int j = 0; j < 4; j++) {
        int i = tid + j * 256;
        int nl = i >> 5, kp = i & 31;
        uint32_t h, l;
        split2(sm[2 * kp][nl], sm[2 * kp + 1][nl], h, l);
        Wh[(size_t)(n0 + nl) * Kp + (k0 >> 1) + kp] = h;
        Wl[(size_t)(n0 + nl) * Kp + (k0 >> 1) + kp] = l;
    }
}

// ---------------- RMSNorm -> split packed output ----------------
__global__ __launch_bounds__(192) void rmsnorm_split_k(const float* __restrict__ in,
                                                       const float* __restrict__ w,
                                                       uint32_t* __restrict__ oh,
                                                       uint32_t* __restrict__ ol) {
    int row = blockIdx.x;
    const float4* p = (const float4*)(in + (size_t)row * DM_);
    float4 v = p[threadIdx.x];
    float ss = v.x * v.x + v.y * v.y + v.z * v.z + v.w * v.w;
    for (int o = 16; o; o >>= 1) ss += __shfl_xor_sync(0xffffffffu, ss, o);
    __shared__ float red[6];
    if ((threadIdx.x & 31) == 0) red[threadIdx.x >> 5] = ss;
    __syncthreads();
    __shared__ float tots;
    if (threadIdx.x == 0) {
        float t = 0.f;
        #pragma unroll
        for (int i = 0; i < 6; i++) t += red[i];
        tots = t;
    }
    __syncthreads();
    float r = rsqrtf(tots / (float)DM_ + EPSF);
    float4 wv = ((const float4*)w)[threadIdx.x];
    uint32_t h0, l0, h1, l1;
    split2(v.x * r * wv.x, v.y * r * wv.y, h0, l0);
    split2(v.z * r * wv.z, v.w * r * wv.w, h1, l1);
    size_t base = (size_t)row * DP_ + 2 * threadIdx.x;
    oh[base] = h0; oh[base + 1] = h1;
    ol[base] = l0; ol[base + 1] = l1;
}

// ---------------- final RMSNorm (float out) ----------------
__global__ __launch_bounds__(192) void rmsnorm_k(const float* __restrict__ in,
                                                 const float* __restrict__ w,
                                                 float* __restrict__ out) {
    int row = blockIdx.x;
    const float4* p = (const float4*)(in + (size_t)row * DM_);
    float4 v = p[threadIdx.x];
    float ss = v.x * v.x + v.y * v.y + v.z * v.z + v.w * v.w;
    for (int o = 16; o; o >>= 1) ss += __shfl_xor_sync(0xffffffffu, ss, o);
    __shared__ float red[6];
    if ((threadIdx.x & 31) == 0) red[threadIdx.x >> 5] = ss;
    __syncthreads();
    __shared__ float tots;
    if (threadIdx.x == 0) {
        float t = 0.f;
        #pragma unroll
        for (int i = 0; i < 6; i++) t += red[i];
        tots = t;
    }
    __syncthreads();
    float r = rsqrtf(tots / (float)DM_ + EPSF);
    float4 wv = ((const float4*)w)[threadIdx.x];
    float4 o4 = make_float4(v.x * r * wv.x, v.y * r * wv.y, v.z * r * wv.z, v.w * r * wv.w);
    ((float4*)(out + (size_t)row * DM_))[threadIdx.x] = o4;
}

// ---------------- GEMM on pre-split operands: 128x128 tile, BK=32 ----------------
// EPI: 0 = store float, 1 = bias+gelu -> split, 2 = 0.5*(x+bias)+R, 3 = +R, 4 = +bias
template <int EPI>
__global__ __launch_bounds__(256) void gemm_sp(const uint32_t* __restrict__ Ah,
                                               const uint32_t* __restrict__ Al,
                                               const uint32_t* __restrict__ Bh,
                                               const uint32_t* __restrict__ Bl,
                                               const float* __restrict__ bias,
                                               const float* __restrict__ R,
                                               float* __restrict__ C,
                                               uint32_t* __restrict__ Ch,
                                               uint32_t* __restrict__ Cl,
                                               int N, int K) {
    __shared__ uint32_t sAh[128][20], sAl[128][20], sBh[128][20], sBl[128][20];
    int tid = threadIdx.x;
    int warp = tid >> 5, lane = tid & 31;
    int wm = warp >> 2, wn = warp & 3;
    int g = lane >> 2, tg = lane & 3;
    int Kp = K >> 1;

    const uint32_t* Abh = Ah + (size_t)blockIdx.y * 128 * Kp;
    const uint32_t* Abl = Al + (size_t)blockIdx.y * 128 * Kp;
    const uint32_t* Bbh = Bh + (size_t)blockIdx.x * 128 * Kp;
    const uint32_t* Bbl = Bl + (size_t)blockIdx.x * 128 * Kp;

    float acc[4][4][4];
    #pragma unroll
    for (int i = 0; i < 4; i++)
        #pragma unroll
        for (int j = 0; j < 4; j++)
            #pragma unroll
            for (int r = 0; r < 4; r++) acc[i][j][r] = 0.f;

    int frow = tid >> 1, fc = (tid & 1) * 8;

    for (int kp0 = 0; kp0 < Kp; kp0 += 16) {
        size_t ao = (size_t)frow * Kp + kp0 + fc;
        *(uint4*)&sAh[frow][fc]     = *(const uint4*)(Abh + ao);
        *(uint4*)&sAh[frow][fc + 4] = *(const uint4*)(Abh + ao + 4);
        *(uint4*)&sAl[frow][fc]     = *(const uint4*)(Abl + ao);
        *(uint4*)&sAl[frow][fc + 4] = *(const uint4*)(Abl + ao + 4);
        *(uint4*)&sBh[frow][fc]     = *(const uint4*)(Bbh + ao);
        *(uint4*)&sBh[frow][fc + 4] = *(const uint4*)(Bbh + ao + 4);
        *(uint4*)&sBl[frow][fc]     = *(const uint4*)(Bbl + ao);
        *(uint4*)&sBl[frow][fc + 4] = *(const uint4*)(Bbl + ao + 4);
        __syncthreads();

        #pragma unroll
        for (int ks = 0; ks < 2; ks++) {
            int k0 = ks * 8;
            uint32_t bh[4][2], bl[4][2];
            #pragma unroll
            for (int j = 0; j < 4; j++) {
                int col = wn * 32 + j * 8 + g;
                bh[j][0] = sBh[col][k0 + tg]; bh[j][1] = sBh[col][k0 + tg + 4];
                bl[j][0] = sBl[col][k0 + tg]; bl[j][1] = sBl[col][k0 + tg + 4];
            }
            #pragma unroll
            for (int i = 0; i < 4; i++) {
                int r = wm * 64 + i * 16 + g;
                uint32_t ah[4] = {sAh[r][k0 + tg], sAh[r + 8][k0 + tg],
                                  sAh[r][k0 + tg + 4], sAh[r + 8][k0 + tg + 4]};
                uint32_t al[4] = {sAl[r][k0 + tg], sAl[r + 8][k0 + tg],
                                  sAl[r][k0 + tg + 4], sAl[r + 8][k0 + tg + 4]};
                #pragma unroll
                for (int j = 0; j < 4; j++) {
                    mma_bf(acc[i][j], ah, bl[j]);
                    mma_bf(acc[i][j], al, bh[j]);
                    mma_bf(acc[i][j], ah, bh[j]);
                }
            }
        }
        __syncthreads();
    }

    #pragma unroll
    for (int i = 0; i < 4; i++) {
        #pragma unroll
        for (int j = 0; j < 4; j++) {
            size_t row0 = (size_t)blockIdx.y * 128 + wm * 64 + i * 16 + g;
            size_t col0 = (size_t)blockIdx.x * 128 + wn * 32 + j * 8 + 2 * tg;
            #pragma unroll
            for (int h = 0; h < 2; h++) {
                size_t row = row0 + h * 8;
                float v0 = acc[i][j][h * 2 + 0];
                float v1 = acc[i][j][h * 2 + 1];
                if (EPI == 1 || EPI == 2 || EPI == 4) { v0 += bias[col0]; v1 += bias[col0 + 1]; }
                if (EPI == 1) {
                    v0 = gelu_tanh(v0); v1 = gelu_tanh(v1);
                    uint32_t hh, ll;
                    split2(v0, v1, hh, ll);
                    size_t pidx = row * (size_t)(N >> 1) + (col0 >> 1);
                    Ch[pidx] = hh; Cl[pidx] = ll;
                } else {
                    if (EPI == 2) {
                        v0 = 0.5f * v0 + R[row * N + col0];
                        v1 = 0.5f * v1 + R[row * N + col0 + 1];
                    }
                    if (EPI == 3) {
                        v0 += R[row * N + col0];
                        v1 += R[row * N + col0 + 1];
                    }
                    *(float2*)&C[row * N + col0] = make_float2(v0, v1);
                }
            }
        }
    }
}

// ---------------- post-QKV: per-head rmsnorm, RoPE, cache + split K write --------
__global__ __launch_bounds__(64) void qkv_post_k(const float* __restrict__ qkv,
                                                 const float* __restrict__ qw,
                                                 const float* __restrict__ kw,
                                                 float* __restrict__ qrot,
                                                 uint32_t* __restrict__ krh,
                                                 uint32_t* __restrict__ krl,
                                                 float* __restrict__ outkv) {
    int row = blockIdx.x;
    int hh = blockIdx.y;
    int d = threadIdx.x;
    int b = row / N_, n = row % N_;
    const float* base = qkv + (size_t)row * (3 * DM_) + hh * (HD_ * 3);
    float q = base[d * 3 + 0], k = base[d * 3 + 1], v = base[d * 3 + 2];
    float q2 = q * q, k2 = k * k;
    for (int o = 16; o; o >>= 1) {
        q2 += __shfl_xor_sync(0xffffffffu, q2, o);
        k2 += __shfl_xor_sync(0xffffffffu, k2, o);
    }
    __shared__ float red[4];
    if ((d & 31) == 0) { red[d >> 5] = q2; red[2 + (d >> 5)] = k2; }
    __syncthreads();
    float qn = q * rsqrtf((red[0] + red[1]) / (float)HD_ + EPSF) * qw[d];
    float kn = k * rsqrtf((red[2] + red[3]) / (float)HD_ + EPSF) * kw[d];
    __shared__ float sq[64], sk[64];
    sq[d] = qn; sk[d] = kn;
    __syncthreads();
    int pos = CACHE_ + n;
    int i = d & 31;
    float inv = __expf(-(float)i * 0.28782313662425572f);
    float ang = (float)pos * inv;
    float c = cosf(ang), s = sinf(ang);
    float qr, kr;
    if (d < 32) { qr = qn * c - sq[d + 32] * s; kr = kn * c - sk[d + 32] * s; }
    else        { qr = qn * c + sq[d - 32] * s; kr = kn * c + sk[d - 32] * s; }
    qrot[(((size_t)b * N_ + n) * NH_ + hh) * HD_ + d] = qr;
    float krn = __shfl_down_sync(0xffffffffu, kr, 1);
    if ((d & 1) == 0) {
        uint32_t h32, l32;
        split2(kr, krn, h32, l32);
        size_t kidx = (((size_t)(b * NH_ + hh)) * KV_ + pos) * 32 + (d >> 1);
        krh[kidx] = h32; krl[kidx] = l32;
    }
    size_t cb = (((size_t)b * KV_ + pos) * 2) * DM_ + hh * HD_ + d;
    outkv[cb] = kn;
    outkv[cb + DM_] = v;
}

// ---------------- cached KV: copy + rope + split K ----------------
__global__ __launch_bounds__(64) void cache_k(const float* __restrict__ cached,
                                              uint32_t* __restrict__ krh,
                                              uint32_t* __restrict__ krl,
                                              float* __restrict__ outkv) {
    int row = blockIdx.x;
    int hh = blockIdx.y;
    int d = threadIdx.x;
    int b = row / CACHE_, p = row % CACHE_;
    size_t src = (((size_t)b * CACHE_ + p) * 2) * DM_ + hh * HD_ + d;
    float k = cached[src], v = cached[src + DM_];
    size_t dst = (((size_t)b * KV_ + p) * 2) * DM_ + hh * HD_ + d;
    outkv[dst] = k;
    outkv[dst + DM_] = v;
    __shared__ float sk[64];
    sk[d] = k;
    __syncthreads();
    int i = d & 31;
    float inv = __expf(-(float)i * 0.28782313662425572f);
    float ang = (float)p * inv;
    float c = cosf(ang), s = sinf(ang);
    float kr = (d < 32) ? (k * c - sk[d + 32] * s) : (k * c + sk[d - 32] * s);
    float krn = __shfl_down_sync(0xffffffffu, kr, 1);
    if ((d & 1) == 0) {
        uint32_t h32, l32;
        split2(kr, krn, h32, l32);
        size_t kidx = (((size_t)(b * NH_ + hh)) * KV_ + p) * 32 + (d >> 1);
        krh[kidx] = h32; krl[kidx] = l32;
    }
}

// ---------------- V transpose + split: out_kv -> [b][h][d][kvp] ----------------
__global__ __launch_bounds__(256) void vsplit_k(const float* __restrict__ outkv,
                                                uint32_t* __restrict__ vh,
                                                uint32_t* __restrict__ vl) {
    __shared__ float sv[64][65];
    int t0 = blockIdx.x * 64;
    int bh = blockIdx.y;
    int b = bh / NH_, hh = bh % NH_;
    int tid = threadIdx.x;
    #pragma unroll
    for (int j = 0; j < 16; j++) {
        int i = tid + j * 256;
        int kvl = i >> 6, d = i & 63;
        sv[kvl][d] = outkv[(((size_t)b * KV_ + t0 + kvl) * 2 + 1) * DM_ + hh * HD_ + d];
    }
    __syncthreads();
    #pragma unroll
    for (int j = 0; j < 8; j++) {
        int i = tid + j * 256;
        int d = i >> 5, p = i & 31;
        uint32_t h32, l32;
        split2(sv[2 * p][d], sv[2 * p + 1][d], h32, l32);
        size_t idx = (((size_t)bh) * HD_ + d) * (KV_ / 2) + (t0 >> 1) + p;
        vh[idx] = h32; vl[idx] = l32;
    }
}

// ---------------- BF16 flash attention on pre-split K/V ----------------
#define FST 36
__global__ __launch_bounds__(128) void flash_bf(const float* __restrict__ Q,
                                                const uint32_t* __restrict__ KRh,
                                                const uint32_t* __restrict__ KRl,
                                                const uint32_t* __restrict__ Vh,
                                                const uint32_t* __restrict__ Vl,
                                                uint32_t* __restrict__ ATh,
                                                uint32_t* __restrict__ ATl) {
    __shared__ uint32_t Ksh[64][FST], Ksl[64][FST];
    __shared__ uint32_t Vsh[64][FST], Vsl[64][FST];
    int q0 = blockIdx.x * 64;
    int hh = blockIdx.y;
    int b = blockIdx.z;
    int tid = threadIdx.x;
    int warp = tid >> 5, lane = tid & 31;
    int g = lane >> 2, tg = lane & 3;
    int bh = b * NH_ + hh;

    uint32_t qh[4][4], ql[4][4];
    {
        const float* Qb = Q + (((size_t)(b * N_ + q0 + warp * 16)) * NH_ + hh) * HD_;
        #pragma unroll
        for (int kt = 0; kt < 4; kt++) {
            float2 x0 = *(const float2*)(Qb + (size_t)g * DM_ + 16 * kt + 2 * tg);
            float2 x1 = *(const float2*)(Qb + (size_t)(g + 8) * DM_ + 16 * kt + 2 * tg);
            float2 x2 = *(const float2*)(Qb + (size_t)g * DM_ + 16 * kt + 2 * tg + 8);
            float2 x3 = *(const float2*)(Qb + (size_t)(g + 8) * DM_ + 16 * kt + 2 * tg + 8);
            split2(x0.x, x0.y, qh[kt][0], ql[kt][0]);
            split2(x1.x, x1.y, qh[kt][1], ql[kt][1]);
            split2(x2.x, x2.y, qh[kt][2], ql[kt][2]);
            split2(x3.x, x3.y, qh[kt][3], ql[kt][3]);
        }
    }

    const uint32_t* KbH = KRh + ((size_t)bh) * KV_ * 32;
    const uint32_t* KbL = KRl + ((size_t)bh) * KV_ * 32;
    const uint32_t* VbH = Vh + ((size_t)bh) * HD_ * (KV_ / 2);
    const uint32_t* VbL = Vl + ((size_t)bh) * HD_ * (KV_ / 2);

    float m0 = -1e30f, m1 = -1e30f, l0 = 0.f, l1 = 0.f;
    float o[8][4];
    #pragma unroll
    for (int j = 0; j < 8; j++)
        #pragma unroll
        for (int r = 0; r < 4; r++) o[j][r] = 0.f;

    const float SC = 0.125f * 1.44269504088896f;

    for (int t = 0; t < KV_; t += 64) {
        int p0 = t >> 1;
        __syncthreads();
        #pragma unroll
        for (int j = 0; j < 4; j++) {
            int e = tid + j * 128;
            int r = e >> 3, c = (e & 7) * 4;
            *(uint4*)&Ksh[r][c] = *(const uint4*)(KbH + (size_t)(t + r) * 32 + c);
            *(uint4*)&Ksl[r][c] = *(const uint4*)(KbL + (size_t)(t + r) * 32 + c);
            *(uint4*)&Vsh[r][c] = *(const uint4*)(VbH + (size_t)r * (KV_ / 2) + p0 + c);
            *(uint4*)&Vsl[r][c] = *(const uint4*)(VbL + (size_t)r * (KV_ / 2) + p0 + c);
        }
        __syncthreads();

        float s[8][4];
        #pragma unroll
        for (int j = 0; j < 8; j++)
            #pragma unroll
            for (int r = 0; r < 4; r++) s[j][r] = 0.f;
        #pragma unroll
        for (int kt = 0; kt < 4; kt++) {
            #pragma unroll
            for (int j = 0; j < 8; j++) {
                int kv = j * 8 + g;
                uint32_t kbh[2] = {Ksh[kv][8 * kt + tg], Ksh[kv][8 * kt + tg + 4]};
                uint32_t kbl[2] = {Ksl[kv][8 * kt + tg], Ksl[kv][8 * kt + tg + 4]};
                mma_bf(s[j], qh[kt], kbl);
                mma_bf(s[j], ql[kt], kbh);
                mma_bf(s[j], qh[kt], kbh);
            }
        }

        float mx0 = -1e30f, mx1 = -1e30f;
        #pragma unroll
        for (int j = 0; j < 8; j++) {
            s[j][0] *= SC; s[j][1] *= SC; s[j][2] *= SC; s[j][3] *= SC;
            mx0 = fmaxf(mx0, fmaxf(s[j][0], s[j][1]));
            mx1 = fmaxf(mx1, fmaxf(s[j][2], s[j][3]));
        }
        mx0 = fmaxf(mx0, __shfl_xor_sync(0xffffffffu, mx0, 1));
        mx0 = fmaxf(mx0, __shfl_xor_sync(0xffffffffu, mx0, 2));
        mx1 = fmaxf(mx1, __shfl_xor_sync(0xffffffffu, mx1, 1));
        mx1 = fmaxf(mx1, __shfl_xor_sync(0xffffffffu, mx1, 2));
        float M0 = fmaxf(m0, mx0), M1 = fmaxf(m1, mx1);
        float a0 = ex2f_(m0 - M0), a1 = ex2f_(m1 - M1);
        m0 = M0; m1 = M1;
        float ls0 = 0.f, ls1 = 0.f;
        #pragma unroll
        for (int j = 0; j < 8; j++) {
            s[j][0] = ex2f_(s[j][0] - M0);
            s[j][1] = ex2f_(s[j][1] - M0);
            s[j][2] = ex2f_(s[j][2] - M1);
            s[j][3] = ex2f_(s[j][3] - M1);
            ls0 += s[j][0] + s[j][1];
            ls1 += s[j][2] + s[j][3];
        }
        ls0 += __shfl_xor_sync(0xffffffffu, ls0, 1);
        ls0 += __shfl_xor_sync(0xffffffffu, ls0, 2);
        ls1 += __shfl_xor_sync(0xffffffffu, ls1, 1);
        ls1 += __shfl_xor_sync(0xffffffffu, ls1, 2);
        l0 = l0 * a0 + ls0;
        l1 = l1 * a1 + ls1;
        #pragma unroll
        for (int j = 0; j < 8; j++) {
            o[j][0] *= a0; o[j][1] *= a0; o[j][2] *= a1; o[j][3] *= a1;
        }

        #pragma unroll
        for (int kt = 0; kt < 4; kt++) {
            uint32_t ph[4], pl[4];
            split2(s[2 * kt][0], s[2 * kt][1], ph[0], pl[0]);
            split2(s[2 * kt][2], s[2 * kt][3], ph[1], pl[1]);
            split2(s[2 * kt + 1][0], s[2 * kt + 1][1], ph[2], pl[2]);
            split2(s[2 * kt + 1][2], s[2 * kt + 1][3], ph[3], pl[3]);
            #pragma unroll
            for (int j = 0; j < 8; j++) {
                int d = j * 8 + g;
                uint32_t vbh[2] = {Vsh[d][8 * kt + tg], Vsh[d][8 * kt + tg + 4]};
                uint32_t vbl[2] = {Vsl[d][8 * kt + tg], Vsl[d][8 * kt + tg + 4]};
                mma_bf(o[j], ph, vbl);
                mma_bf(o[j], pl, vbh);
                mma_bf(o[j], ph, vbh);
            }
        }
    }

    float il0 = 1.f / l0, il1 = 1.f / l1;
    size_t r0 = (size_t)(b * N_ + q0 + warp * 16 + g) * DP_;
    size_t r1 = (size_t)(b * N_ + q0 + warp * 16 + g + 8) * DP_;
    #pragma unroll
    for (int j = 0; j < 8; j++) {
        int pidx = hh * 32 + j * 4 + tg;
        uint32_t h32, l32;
        split2(o[j][0] * il0, o[j][1] * il0, h32, l32);
        ATh[r0 + pidx] = h32; ATl[r0 + pidx] = l32;
        split2(o[j][2] * il1, o[j][3] * il1, h32, l32);
        ATh[r1 + pidx] = h32; ATl[r1 + pidx] = l32;
    }
}

// ---------------- GLU ----------------
__global__ void glu_k(const float* __restrict__ in, float* __restrict__ out) {
    size_t idx = (size_t)blockIdx.x * blockDim.x + threadIdx.x;
    if (idx >= (size_t)ROWS_ * DM_ / 4) return;
    size_t r = idx / (DM_ / 4), c = idx % (DM_ / 4);
    const float4* in4 = (const float4*)in;
    float4 a = in4[r * (2 * DM_ / 4) + c];
    float4 bb = in4[r * (2 * DM_ / 4) + (DM_ / 4) + c];
    float4 o4 = make_float4(a.x * sigmoidf_(bb.x), a.y * sigmoidf_(bb.y),
                            a.z * sigmoidf_(bb.z), a.w * sigmoidf_(bb.w));
    ((float4*)out)[idx] = o4;
}

// ---------------- depthwise conv1d, smem-tiled 64t x 128c ----------------
__global__ __launch_bounds__(256) void dwconv_k(const float* __restrict__ in,
                                                const float* __restrict__ wt,
                                                const float* __restrict__ bias,
                                                float* __restrict__ out) {
    __shared__ float s[94 * 128];
    int t0 = blockIdx.x * 64, c0 = blockIdx.y * 128, b = blockIdx.z;
    int tid = threadIdx.x;
    for (int i = tid; i < 94 * 128; i += 256) {
        int tl = i >> 7, c = i & 127;
        int tg_ = t0 + tl - 15;
        s[i] = (tg_ >= 0 && tg_ < N_) ? in[((size_t)b * N_ + tg_) * DM_ + c0 + c] : 0.f;
    }
    __syncthreads();
    int c = tid & 127;
    float w[KSZ_];
    #pragma unroll
    for (int kk = 0; kk < KSZ_; kk++) w[kk] = wt[(size_t)(c0 + c) * KSZ_ + kk];
    float bsv = bias[c0 + c];
    int tb = tid >> 7;
    #pragma unroll 4
    for (int k = 0; k < 32; k++) {
        int tl = tb + 2 * k;
        float acc = bsv;
        #pragma unroll
        for (int kk = 0; kk < KSZ_; kk++)
            acc = fmaf(s[(tl + kk) * 128 + c], w[kk], acc);
        out[((size_t)b * N_ + t0 + tl) * DM_ + c0 + c] = acc;
    }
}

// ---------------- batchnorm stats ----------------
__global__ __launch_bounds__(256) void bnstats_k(const float* __restrict__ in,
                                                 float* __restrict__ stats) {
    int tx = threadIdx.x & 31, ty = threadIdx.x >> 5;
    int c = blockIdx.x * 32 + tx;
    double s = 0.0, ss = 0.0;
    for (int r = ty; r < ROWS_; r += 8) {
        float v = in[(size_t)r * DM_ + c];
        s += v; ss += (double)v * v;
    }
    __shared__ double sh_s[8][33], sh_ss[8][33];
    sh_s[ty][tx] = s; sh_ss[ty][tx] = ss;
    __syncthreads();
    if (ty == 0) {
        #pragma unroll
        for (int i = 1; i < 8; i++) { s += sh_s[i][tx]; ss += sh_ss[i][tx]; }
        double mean = s / (double)ROWS_;
        double var = ss / (double)ROWS_ - mean * mean;
        stats[c] = (float)mean;
        stats[DM_ + c] = rsqrtf((float)var + EPSF);
    }
}

// ---------------- batchnorm apply + swish -> split output ----------------
__global__ void bnapply_k(const float* __restrict__ in, const float* __restrict__ stats,
                          const float* __restrict__ g, const float* __restrict__ bb,
                          uint32_t* __restrict__ oh, uint32_t* __restrict__ ol) {
    size_t idx = (size_t)blockIdx.x * blockDim.x + threadIdx.x;
    if (idx >= (size_t)ROWS_ * DM_ / 4) return;
    size_t row = idx / (DM_ / 4);
    int c4 = (int)(idx % (DM_ / 4));
    int c = c4 * 4;
    float4 v = ((const float4*)in)[idx];
    float y0, y1, y2, y3;
    y0 = (v.x - stats[c + 0]) * stats[DM_ + c + 0] * g[c + 0] + bb[c + 0]; y0 = y0 * sigmoidf_(y0);
    y1 = (v.y - stats[c + 1]) * stats[DM_ + c + 1] * g[c + 1] + bb[c + 1]; y1 = y1 * sigmoidf_(y1);
    y2 = (v.z - stats[c + 2]) * stats[DM_ + c + 2] * g[c + 2] + bb[c + 2]; y2 = y2 * sigmoidf_(y2);
    y3 = (v.w - stats[c + 3]) * stats[DM_ + c + 3] * g[c + 3] + bb[c + 3]; y3 = y3 * sigmoidf_(y3);
    uint32_t h0, l0, h1, l1;
    split2(y0, y1, h0, l0);
    split2(y2, y3, h1, l1);
    size_t base = row * DP_ + 2 * c4;
    oh[base] = h0; oh[base + 1] = h1;
    ol[base] = l0; ol[base + 1] = l1;
}

// ---------------- host launcher ----------------
extern "C" void kernel_launch(void* const* d_in, const int* in_sizes, int n_in,
                              void* d_out, int out_size) {
    (void)out_size;
    const float* x = (const float*)d_in[0];
    int ikv = 4;
    for (int i = 1; i < n_in; i++)
        if (in_sizes[i] == 786432) { ikv = i; break; }
    const float* cached_kv = (const float*)d_in[ikv];
    int w = ikv + 1;
    const float* ff1_norm_w = (const float*)d_in[w + 0];
    const float* ff1_w1     = (const float*)d_in[w + 1];
    const float* ff1_b1     = (const float*)d_in[w + 2];
    const float* ff1_w2     = (const float*)d_in[w + 3];
    const float* ff1_b2     = (const float*)d_in[w + 4];
    const float* attn_norm_w= (const float*)d_in[w + 5];
    const float* qkv_w      = (const float*)d_in[w + 6];
    const float* out_w      = (const float*)d_in[w + 7];
    const float* q_norm_w   = (const float*)d_in[w + 8];
    const float* k_norm_w   = (const float*)d_in[w + 9];
    const float* conv_norm_w= (const float*)d_in[w + 10];
    const float* pw1_w      = (const float*)d_in[w + 11];
    const float* pw1_b      = (const float*)d_in[w + 12];
    const float* dw_w       = (const float*)d_in[w + 13];
    const float* dw_b       = (const float*)d_in[w + 14];
    const float* bn_g       = (const float*)d_in[w + 15];
    const float* bn_b       = (const float*)d_in[w + 16];
    const float* pw2_w      = (const float*)d_in[w + 17];
    const float* pw2_b      = (const float*)d_in[w + 18];
    const float* ff2_norm_w = (const float*)d_in[w + 19];
    const float* ff2_w1     = (const float*)d_in[w + 20];
    const float* ff2_b1     = (const float*)d_in[w + 21];
    const float* ff2_w2     = (const float*)d_in[w + 22];
    const float* ff2_b2     = (const float*)d_in[w + 23];
    const float* out_norm_w = (const float*)d_in[w + 24];

    float* out_x  = (float*)d_out;
    float* out_kv = out_x + (size_t)B_ * N_ * DM_;

    float *S0, *S2f, *QR, *C1f, *C2f, *BN;
    uint32_t *S1h, *S1l, *S2h, *S2l, *ATh, *ATl, *C1h, *C1l, *KRh, *KRl, *Vh, *Vl, *Wh, *Wl;
    cudaGetSymbolAddress((void**)&S0, g_S0);
    cudaGetSymbolAddress((void**)&S2f, g_S2f);
    cudaGetSymbolAddress((void**)&QR, g_QR);
    cudaGetSymbolAddress((void**)&C1f, g_C1f);
    cudaGetSymbolAddress((void**)&C2f, g_C2f);
    cudaGetSymbolAddress((void**)&BN, g_bn);
    cudaGetSymbolAddress((void**)&S1h, g_S1h);
    cudaGetSymbolAddress((void**)&S1l, g_S1l);
    cudaGetSymbolAddress((void**)&S2h, g_S2h);
    cudaGetSymbolAddress((void**)&S2l, g_S2l);
    cudaGetSymbolAddress((void**)&ATh, g_ATh);
    cudaGetSymbolAddress((void**)&ATl, g_ATl);
    cudaGetSymbolAddress((void**)&C1h, g_C1h);
    cudaGetSymbolAddress((void**)&C1l, g_C1l);
    cudaGetSymbolAddress((void**)&KRh, g_KRh);
    cudaGetSymbolAddress((void**)&KRl, g_KRl);
    cudaGetSymbolAddress((void**)&Vh, g_Vh);
    cudaGetSymbolAddress((void**)&Vl, g_Vl);
    cudaGetSymbolAddress((void**)&Wh, g_Wh);
    cudaGetSymbolAddress((void**)&Wl, g_Wl);

    // weight split offsets (uint32 pair counts)
    const size_t oFF1W1 = 0,        oFF1W2 = 1179648, oQKV = 2359296, oOUT = 3244032;
    const size_t oPW1 = 3538944,    oPW2 = 4128768,   oFF2W1 = 4423680, oFF2W2 = 5603328;

    wsplit_k<<<dim3(DM_ / 64, FF_ / 32), 256>>>(ff1_w1, Wh + oFF1W1, Wl + oFF1W1, DM_, FF_);
    wsplit_k<<<dim3(FF_ / 64, DM_ / 32), 256>>>(ff1_w2, Wh + oFF1W2, Wl + oFF1W2, FF_, DM_);
    wsplit_k<<<dim3(DM_ / 64, 2304 / 32), 256>>>(qkv_w, Wh + oQKV, Wl + oQKV, DM_, 2304);
    wsplit_k<<<dim3(DM_ / 64, DM_ / 32), 256>>>(out_w, Wh + oOUT, Wl + oOUT, DM_, DM_);
    wsplit_k<<<dim3(DM_ / 64, 1536 / 32), 256>>>(pw1_w, Wh + oPW1, Wl + oPW1, DM_, 1536);
    wsplit_k<<<dim3(DM_ / 64, DM_ / 32), 256>>>(pw2_w, Wh + oPW2, Wl + oPW2, DM_, DM_);
    wsplit_k<<<dim3(DM_ / 64, FF_ / 32), 256>>>(ff2_w1, Wh + oFF2W1, Wl + oFF2W1, DM_, FF_);
    wsplit_k<<<dim3(FF_ / 64, DM_ / 32), 256>>>(ff2_w2, Wh + oFF2W2, Wl + oFF2W2, FF_, DM_);

    const int EW4_GRID = (int)(((size_t)ROWS_ * DM_ / 4 + 255) / 256);

    // ---- FF1 ----
    rmsnorm_split_k<<<ROWS_, 192>>>(x, ff1_norm_w, S1h, S1l);
    gemm_sp<1><<<dim3(FF_ / 128, ROWS_ / 128), 256>>>(S1h, S1l, Wh + oFF1W1, Wl + oFF1W1,
        ff1_b1, nullptr, nullptr, S2h, S2l, FF_, DM_);
    gemm_sp<2><<<dim3(DM_ / 128, ROWS_ / 128), 256>>>(S2h, S2l, Wh + oFF1W2, Wl + oFF1W2,
        ff1_b2, x, S0, nullptr, nullptr, DM_, FF_);

    // ---- attention ----
    rmsnorm_split_k<<<ROWS_, 192>>>(S0, attn_norm_w, S1h, S1l);
    gemm_sp<0><<<dim3(2304 / 128, ROWS_ / 128), 256>>>(S1h, S1l, Wh + oQKV, Wl + oQKV,
        nullptr, nullptr, S2f, nullptr, nullptr, 2304, DM_);
    qkv_post_k<<<dim3(ROWS_, NH_), 64>>>(S2f, q_norm_w, k_norm_w, QR, KRh, KRl, out_kv);
    cache_k<<<dim3(B_ * CACHE_, NH_), 64>>>(cached_kv, KRh, KRl, out_kv);
    vsplit_k<<<dim3(KV_ / 64, B_ * NH_), 256>>>(out_kv, Vh, Vl);
    flash_bf<<<dim3(N_ / 64, NH_, B_), 128>>>(QR, KRh, KRl, Vh, Vl, ATh, ATl);
    gemm_sp<3><<<dim3(DM_ / 128, ROWS_ / 128), 256>>>(ATh, ATl, Wh + oOUT, Wl + oOUT,
        nullptr, S0, S0, nullptr, nullptr, DM_, DM_);

    // ---- conv module ----
    rmsnorm_split_k<<<ROWS_, 192>>>(S0, conv_norm_w, S1h, S1l);
    gemm_sp<4><<<dim3(1536 / 128, ROWS_ / 128), 256>>>(S1h, S1l, Wh + oPW1, Wl + oPW1,
        pw1_b, nullptr, S2f, nullptr, nullptr, 1536, DM_);
    glu_k<<<EW4_GRID, 256>>>(S2f, C1f);
    dwconv_k<<<dim3(N_ / 64, DM_ / 128, B_), 256>>>(C1f, dw_w, dw_b, C2f);
    bnstats_k<<<DM_ / 32, 256>>>(C2f, BN);
    bnapply_k<<<EW4_GRID, 256>>>(C2f, BN, bn_g, bn_b, C1h, C1l);
    gemm_sp<4><<<dim3(DM_ / 128, ROWS_ / 128), 256>>>(C1h, C1l, Wh + oPW2, Wl + oPW2,
        pw2_b, nullptr, S0, nullptr, nullptr, DM_, DM_);

    // ---- FF2 ----
    rmsnorm_split_k<<<ROWS_, 192>>>(S0, ff2_norm_w, S1h, S1l);
    gemm_sp<1><<<dim3(FF_ / 128, ROWS_ / 128), 256>>>(S1h, S1l, Wh + oFF2W1, Wl + oFF2W1,
        ff2_b1, nullptr, nullptr, S2h, S2l, FF_, DM_);
    gemm_sp<2><<<dim3(DM_ / 128, ROWS_ / 128), 256>>>(S2h, S2l, Wh + oFF2W2, Wl + oFF2W2,
        ff2_b2, S0, S0, nullptr, nullptr, DM_, FF_);

    // ---- final norm ----
    rmsnorm_k<<<ROWS_, 192>>>(S0, out_norm_w, out_x);
}